// round 1
// baseline (speedup 1.0000x reference)
#include <cuda_runtime.h>
#include <math.h>

#define Bb   4
#define Lseq 2048
#define Dm   1024
#define Hh   4
#define DHd  256
#define CHK  32
#define NCk  (Lseq/CHK)      // 64
#define Mrows (Bb*Lseq)      // 8192
#define MD (Mrows*Dm)

// ---------------- scratch (static device globals; no allocation) ----------------
__device__ float g_qlin[MD], g_klin[MD], g_vlin[MD];
__device__ float g_q[MD], g_k[MD], g_v[MD];
__device__ float g_u[MD], g_w[MD];
__device__ float g_A2[Bb*Hh*NCk*CHK*CHK];
__device__ float g_beta[Mrows*Hh], g_gamma[Mrows*Hh], g_mixlin[Mrows*Hh], g_mix[Mrows*Hh];
__device__ float g_od[MD], g_ema[MD], g_oc[MD];

__device__ __forceinline__ float sigm(float x){ return 1.0f/(1.0f+__expf(-x)); }

// ---------------- tiled SGEMM: C[M,N] = A[M,K] @ B[K,N], all row-major ----------
__global__ __launch_bounds__(256) void sgemm_kernel(const float* __restrict__ A,
                                                    const float* __restrict__ B,
                                                    float* __restrict__ C,
                                                    int Mr, int Nr, int Kr)
{
    __shared__ float As[16][128];
    __shared__ float Bs[16][128];
    int tid = threadIdx.x;
    int tr = tid >> 4, tc = tid & 15;          // 16x16 thread tile, 8x8 each
    const float* Ab = A + (size_t)blockIdx.y * 128 * Kr;
    const float* Bp = B + (size_t)blockIdx.x * 128;

    float acc[8][8];
#pragma unroll
    for (int i=0;i<8;i++)
#pragma unroll
        for (int j=0;j<8;j++) acc[i][j]=0.0f;

    int arow = tid >> 2, acol = (tid & 3) * 4;   // A tile loads
    int brow = tid >> 5, bcol = (tid & 31) * 4;  // B tile loads

    for (int k0 = 0; k0 < Kr; k0 += 16){
        float4 a0 = *(const float4*)(Ab + (size_t)arow*Kr + k0 + acol);
        float4 a1 = *(const float4*)(Ab + (size_t)(arow+64)*Kr + k0 + acol);
        As[acol+0][arow]=a0.x; As[acol+1][arow]=a0.y; As[acol+2][arow]=a0.z; As[acol+3][arow]=a0.w;
        As[acol+0][arow+64]=a1.x; As[acol+1][arow+64]=a1.y; As[acol+2][arow+64]=a1.z; As[acol+3][arow+64]=a1.w;
        float4 b0 = *(const float4*)(Bp + (size_t)(k0+brow)*Nr + bcol);
        float4 b1 = *(const float4*)(Bp + (size_t)(k0+brow+8)*Nr + bcol);
        *(float4*)&Bs[brow][bcol]   = b0;
        *(float4*)&Bs[brow+8][bcol] = b1;
        __syncthreads();
#pragma unroll
        for (int kk=0; kk<16; kk++){
            float ra[8], rb[8];
            *(float4*)&ra[0] = *(float4*)&As[kk][tr*8];
            *(float4*)&ra[4] = *(float4*)&As[kk][tr*8+4];
            *(float4*)&rb[0] = *(float4*)&Bs[kk][tc*8];
            *(float4*)&rb[4] = *(float4*)&Bs[kk][tc*8+4];
#pragma unroll
            for (int i=0;i<8;i++)
#pragma unroll
                for (int j=0;j<8;j++) acc[i][j] += ra[i]*rb[j];
        }
        __syncthreads();
    }
    float* Cb = C + (size_t)(blockIdx.y*128 + tr*8)*Nr + blockIdx.x*128 + tc*8;
#pragma unroll
    for (int i=0;i<8;i++){
        *(float4*)(Cb + (size_t)i*Nr)     = make_float4(acc[i][0],acc[i][1],acc[i][2],acc[i][3]);
        *(float4*)(Cb + (size_t)i*Nr + 4) = make_float4(acc[i][4],acc[i][5],acc[i][6],acc[i][7]);
    }
}

// ---------------- small projections: beta/gamma/mixlin ----------------
__global__ __launch_bounds__(256) void proj_small_kernel(const float* __restrict__ X,
                                                         const float* __restrict__ Wb_,
                                                         const float* __restrict__ Wd_,
                                                         const float* __restrict__ Wm_)
{
    int t = blockIdx.x, tid = threadIdx.x, lane = tid & 31, wid = tid >> 5;
    float acc[12];
#pragma unroll
    for (int i=0;i<12;i++) acc[i]=0.0f;
    for (int e=tid; e<Dm; e+=256){
        float xv = X[(size_t)t*Dm + e];
#pragma unroll
        for (int c=0;c<4;c++){
            acc[c]   += xv*Wb_[e*4+c];
            acc[4+c] += xv*Wd_[e*4+c];
            acc[8+c] += xv*Wm_[e*4+c];
        }
    }
    __shared__ float red[12][8];
#pragma unroll
    for (int i=0;i<12;i++){
        float s = acc[i];
        for (int o=16;o;o>>=1) s += __shfl_xor_sync(0xffffffffu, s, o);
        if (lane==0) red[i][wid]=s;
    }
    __syncthreads();
    if (tid < 12){
        float s = 0.0f;
        for (int w=0;w<8;w++) s += red[tid][w];
        if (tid < 4)       g_beta[t*Hh + tid]      = sigm(s);
        else if (tid < 8)  g_gamma[t*Hh + (tid-4)] = sigm(s);
        else               g_mixlin[t*Hh + (tid-8)] = s;
    }
}

// ---------------- depthwise causal conv + silu (optionally double silu) --------
__global__ void conv_silu_kernel(const float* __restrict__ lin, const float* __restrict__ cw,
                                 float* __restrict__ out, int dsilu)
{
    int e = blockIdx.x*blockDim.x + threadIdx.x;
    if (e >= MD) return;
    int t = e / Dm, c = e % Dm;
    int tl = t % Lseq;
    float w0=cw[c*4+0], w1=cw[c*4+1], w2=cw[c*4+2], w3=cw[c*4+3];
    float acc = lin[e]*w3;
    if (tl>=1) acc += lin[e-Dm]*w2;
    if (tl>=2) acc += lin[e-2*Dm]*w1;
    if (tl>=3) acc += lin[e-3*Dm]*w0;
    float y = acc * sigm(acc);
    if (dsilu) y = y * sigm(y);
    out[e] = y;
}

__global__ void conv_mix_kernel(const float* __restrict__ cm, const float* __restrict__ mbias)
{
    int e = blockIdx.x*blockDim.x + threadIdx.x;
    if (e >= Mrows*Hh) return;
    int t = e / Hh, h = e % Hh;
    int tl = t % Lseq;
    float w0=cm[h*4+0], w1=cm[h*4+1], w2=cm[h*4+2], w3=cm[h*4+3];
    float acc = g_mixlin[e]*w3;
    if (tl>=1) acc += g_mixlin[e-Hh]*w2;
    if (tl>=2) acc += g_mixlin[e-2*Hh]*w1;
    if (tl>=3) acc += g_mixlin[e-3*Hh]*w0;
    float y = acc * sigm(acc);             // silu
    g_mix[e] = sigm(y + mbias[h]);
}

// ---------------- per-chunk precompute: l2norm, T (fwd-subst), u, w, A2 --------
// grid = Bb*Hh*NCk blocks, 256 threads, dynamic smem
__global__ __launch_bounds__(256) void chunk_pre_kernel()
{
    extern __shared__ float sm4[];
    float* sq  = sm4;               // 32*257
    float* skk = sq  + 32*257;      // 32*257
    float* sT  = skk + 32*257;      // 1024
    float* sb  = sT  + 1024;        // 32
    int z = blockIdx.x;
    int b  = z >> 8;                // /(Hh*NCk)=256
    int h  = (z >> 6) & 3;
    int nc = z & 63;
    int t0 = b*Lseq + nc*CHK;
    int cb = h*DHd;
    int tid = threadIdx.x, lane = tid & 31, wid = tid >> 5;

    for (int e=tid; e<32*256; e+=256){
        int r=e>>8, c=e&255;
        sq [r*257+c] = g_q[(size_t)(t0+r)*Dm + cb + c];
        skk[r*257+c] = g_k[(size_t)(t0+r)*Dm + cb + c];
    }
    if (tid < 32) sb[tid] = g_beta[(t0+tid)*Hh + h];
    __syncthreads();

    // row l2norm for q and k; write normalized back to global for the recurrence
    for (int r=wid; r<32; r+=8){
        float s=0.0f;
        for (int c=lane;c<256;c+=32){ float v=sq[r*257+c]; s+=v*v; }
        for (int o=16;o;o>>=1) s += __shfl_xor_sync(0xffffffffu,s,o);
        float rn = rsqrtf(s + 1e-6f);
        for (int c=lane;c<256;c+=32){ float v=sq[r*257+c]*rn; sq[r*257+c]=v; g_q[(size_t)(t0+r)*Dm+cb+c]=v; }
        s=0.0f;
        for (int c=lane;c<256;c+=32){ float v=skk[r*257+c]; s+=v*v; }
        for (int o=16;o;o>>=1) s += __shfl_xor_sync(0xffffffffu,s,o);
        rn = rsqrtf(s + 1e-6f);
        for (int c=lane;c<256;c+=32){ float v=skk[r*257+c]*rn; skk[r*257+c]=v; g_k[(size_t)(t0+r)*Dm+cb+c]=v; }
    }
    __syncthreads();

    // attn = -(k_beta @ k^T) strict lower
    for (int e=tid; e<1024; e+=256){
        int i=e>>5, j=e&31;
        float val=0.0f;
        if (j < i){
            float s=0.0f;
            for (int p=0;p<256;p++) s += skk[i*257+p]*skk[j*257+p];
            val = -sb[i]*s;
        }
        sT[e]=val;
    }
    __syncthreads();

    // forward substitution (warp 0), then +I
    if (wid == 0){
        for (int i=1;i<32;i++){
            float a = sT[i*32+lane];
            float acc = 0.0f;
            for (int j=1;j<32;j++){
                float aij = __shfl_sync(0xffffffffu, a, j);
                acc += aij * sT[j*32+lane];
            }
            if (lane < i) sT[i*32+lane] = a + acc;
            __syncwarp();
        }
        sT[lane*32+lane] += 1.0f;
    }
    __syncthreads();

    // A2 = tril(q @ k^T) inclusive
    int abase = z*1024;
    for (int e=tid; e<1024; e+=256){
        int i=e>>5, j=e&31;
        float val=0.0f;
        if (j <= i){
            float s=0.0f;
            for (int p=0;p<256;p++) s += sq[i*257+p]*skk[j*257+p];
            val = s;
        }
        g_A2[abase+e]=val;
    }

    // u = T @ (v*beta),  w = T @ (k*beta)
    for (int e=tid; e<32*256; e+=256){
        int i=e>>8, c=e&255;
        float uu=0.0f, ww=0.0f;
        for (int j=0;j<32;j++){
            float tb = sT[i*32+j]*sb[j];
            uu += tb * g_v[(size_t)(t0+j)*Dm + cb + c];
            ww += tb * skk[j*257+c];
        }
        g_u[(size_t)(t0+i)*Dm+cb+c]=uu;
        g_w[(size_t)(t0+i)*Dm+cb+c]=ww;
    }
}

// ---------------- sequential inter-chunk recurrence, dv-sliced ----------------
// grid = Bb*Hh*8 (dv slices of 32), 256 threads, dynamic smem
__global__ __launch_bounds__(256) void recurrence_kernel()
{
    extern __shared__ float sm5[];
    float* S   = sm5;             // 256*32
    float* swv = S   + 8192;      // 32*260
    float* sqv = swv + 32*260;
    float* skv = sqv + 32*260;
    float* su  = skv + 32*260;    // 32*32
    float* sA  = su  + 1024;      // 32*32
    float* sua = sA  + 1024;      // 32*32
    float* sR  = sua + 1024;      // 64*32

    int bx = blockIdx.x;
    int bh = bx >> 3, vb = bx & 7;
    int b = bh >> 2, h = bh & 3;
    int cb  = h*DHd;
    int cvb = cb + vb*32;
    int tid = threadIdx.x;
    int tr = tid >> 3, tc = tid & 7;
    const float* Amat = (tr < 16) ? swv : sqv;
    int r0 = (tr & 15)*2;

    for (int i=tid; i<8192; i+=256) S[i]=0.0f;
    __syncthreads();

    for (int ci=0; ci<NCk; ci++){
        int t0 = b*Lseq + ci*CHK;
        for (int e=tid; e<32*256; e+=256){
            int r=e>>8, c=e&255;
            size_t gi = (size_t)(t0+r)*Dm + cb + c;
            swv[r*260+c] = g_w[gi];
            sqv[r*260+c] = g_q[gi];
            skv[r*260+c] = g_k[gi];
        }
        for (int e=tid; e<1024; e+=256){
            int r=e>>5, c=e&31;
            su[e] = g_u[(size_t)(t0+r)*Dm + cvb + c];
            sA[e] = g_A2[(size_t)(bh*NCk+ci)*1024 + e];
        }
        __syncthreads();

        // R = [W;Q] @ S   (64 x 32)
        {
            float4 acc0 = make_float4(0,0,0,0), acc1 = acc0;
#pragma unroll 4
            for (int p=0;p<256;p++){
                float a0 = Amat[r0*260+p];
                float a1 = Amat[(r0+1)*260+p];
                float4 sv = *(float4*)&S[p*32 + tc*4];
                acc0.x += a0*sv.x; acc0.y += a0*sv.y; acc0.z += a0*sv.z; acc0.w += a0*sv.w;
                acc1.x += a1*sv.x; acc1.y += a1*sv.y; acc1.z += a1*sv.z; acc1.w += a1*sv.w;
            }
            int rr = tr*2;
            *(float4*)&sR[rr*32     + tc*4] = acc0;
            *(float4*)&sR[(rr+1)*32 + tc*4] = acc1;
        }
        __syncthreads();

        for (int e=tid; e<1024; e+=256) sua[e] = su[e] - sR[e];   // u_adj
        __syncthreads();

        // o = Q@S + A2 @ u_adj  -> global
        {
            int c = tid & 31, iw = tid >> 5;
#pragma unroll
            for (int rep=0;rep<4;rep++){
                int i = iw + rep*8;
                float o = sR[(32+i)*32 + c];
                for (int j=0;j<32;j++) o += sA[i*32+j]*sua[j*32+c];
                g_od[(size_t)(t0+i)*Dm + cvb + c] = o;
            }
        }

        // S += K^T @ u_adj
        {
            float4 acc[8];
#pragma unroll
            for (int m=0;m<8;m++) acc[m] = *(float4*)&S[(tr+32*m)*32 + tc*4];
            for (int j=0;j<32;j++){
                float4 b4 = *(float4*)&sua[j*32 + tc*4];
#pragma unroll
                for (int m=0;m<8;m++){
                    float a = skv[j*260 + tr + 32*m];
                    acc[m].x += a*b4.x; acc[m].y += a*b4.y; acc[m].z += a*b4.z; acc[m].w += a*b4.w;
                }
            }
#pragma unroll
            for (int m=0;m<8;m++) *(float4*)&S[(tr+32*m)*32 + tc*4] = acc[m];
        }
        __syncthreads();
    }
}

// ---------------- EMA scan over sequence ----------------
__global__ void ema_kernel()
{
    int bh = blockIdx.x;
    int b = bh >> 2, h = bh & 3;
    int cb = h*DHd;
    int c = threadIdx.x;
    float s = 0.0f;
    for (int t=0;t<Lseq;t++){
        int row = b*Lseq + t;
        float g = g_gamma[row*Hh + h];
        float v = g_v[(size_t)row*Dm + cb + c];
        s = g*s + (1.0f-g)*v;
        g_ema[(size_t)row*Dm + cb + c] = s;
    }
}

// ---------------- mix + rmsnorm ----------------
__global__ __launch_bounds__(256) void combine_kernel(const float* __restrict__ rmsw)
{
    int t = blockIdx.x, c = threadIdx.x;
    __shared__ float red[8];
    for (int h=0;h<Hh;h++){
        float mix = g_mix[t*Hh+h];
        size_t idx = (size_t)t*Dm + h*DHd + c;
        float o = (1.0f-mix)*g_od[idx] + mix*g_ema[idx];
        float s = o*o;
        for (int off=16;off;off>>=1) s += __shfl_xor_sync(0xffffffffu,s,off);
        if ((c&31)==0) red[c>>5]=s;
        __syncthreads();
        float tot = red[0]+red[1]+red[2]+red[3]+red[4]+red[5]+red[6]+red[7];
        float scale = rsqrtf(tot*(1.0f/256.0f) + 1e-5f);
        g_oc[idx] = o*scale*rmsw[c];
        __syncthreads();
    }
}

// ---------------- launcher ----------------
extern "C" void kernel_launch(void* const* d_in, const int* in_sizes, int n_in,
                              void* d_out, int out_size)
{
    const float* X    = (const float*)d_in[0];
    const float* Wq   = (const float*)d_in[1];
    const float* Wk   = (const float*)d_in[2];
    const float* Wv   = (const float*)d_in[3];
    const float* cq   = (const float*)d_in[4];
    const float* ck   = (const float*)d_in[5];
    const float* cv   = (const float*)d_in[6];
    const float* Wb   = (const float*)d_in[7];
    const float* Wdec = (const float*)d_in[8];
    const float* Wmix = (const float*)d_in[9];
    const float* cmix = (const float*)d_in[10];
    const float* mbias= (const float*)d_in[11];
    const float* rmsw = (const float*)d_in[12];
    const float* Wo   = (const float*)d_in[13];
    float* out = (float*)d_out;
    (void)in_sizes; (void)n_in; (void)out_size;

    float *p_qlin,*p_klin,*p_vlin,*p_q,*p_k,*p_v,*p_oc;
    cudaGetSymbolAddress((void**)&p_qlin, g_qlin);
    cudaGetSymbolAddress((void**)&p_klin, g_klin);
    cudaGetSymbolAddress((void**)&p_vlin, g_vlin);
    cudaGetSymbolAddress((void**)&p_q,    g_q);
    cudaGetSymbolAddress((void**)&p_k,    g_k);
    cudaGetSymbolAddress((void**)&p_v,    g_v);
    cudaGetSymbolAddress((void**)&p_oc,   g_oc);

    dim3 gg(Dm/128, Mrows/128);
    sgemm_kernel<<<gg,256>>>(X, Wq, p_qlin, Mrows, Dm, Dm);
    sgemm_kernel<<<gg,256>>>(X, Wk, p_klin, Mrows, Dm, Dm);
    sgemm_kernel<<<gg,256>>>(X, Wv, p_vlin, Mrows, Dm, Dm);
    proj_small_kernel<<<Mrows,256>>>(X, Wb, Wdec, Wmix);

    conv_silu_kernel<<<MD/256,256>>>(p_qlin, cq, p_q, 1);
    conv_silu_kernel<<<MD/256,256>>>(p_klin, ck, p_k, 1);
    conv_silu_kernel<<<MD/256,256>>>(p_vlin, cv, p_v, 0);
    conv_mix_kernel<<<(Mrows*Hh+255)/256,256>>>(cmix, mbias);

    const int SMEM4 = (2*(32*257) + 1024 + 32) * 4;     // 70016 B
    cudaFuncSetAttribute(chunk_pre_kernel, cudaFuncAttributeMaxDynamicSharedMemorySize, SMEM4);
    chunk_pre_kernel<<<Bb*Hh*NCk, 256, SMEM4>>>();

    const int SMEM5 = (8192 + 3*(32*260) + 3*1024 + 2048) * 4;  // 153088 B
    cudaFuncSetAttribute(recurrence_kernel, cudaFuncAttributeMaxDynamicSharedMemorySize, SMEM5);
    recurrence_kernel<<<Bb*Hh*8, 256, SMEM5>>>();

    ema_kernel<<<Bb*Hh, 256>>>();
    combine_kernel<<<Mrows,256>>>(rmsw);

    sgemm_kernel<<<gg,256>>>(p_oc, Wo, out, Mrows, Dm, Dm);
}

// round 3
// speedup vs baseline: 1.3693x; 1.3693x over previous
#include <cuda_runtime.h>
#include <cuda_bf16.h>
#include <math.h>
#include <stdint.h>

#define Bb   4
#define Lseq 2048
#define Dm   1024
#define Hh   4
#define DHd  256
#define CHK  32
#define NCk  (Lseq/CHK)      // 64
#define Mrows (Bb*Lseq)      // 8192
#define MD (Mrows*Dm)

// ---------------- scratch (static device globals; no allocation) ----------------
__device__ float g_qlin[MD], g_klin[MD], g_vlin[MD];
__device__ float g_q[MD], g_k[MD], g_v[MD];
__device__ float g_u[MD], g_w[MD];
__device__ float g_A2[Bb*Hh*NCk*CHK*CHK];
__device__ float g_beta[Mrows*Hh], g_gamma[Mrows*Hh], g_mixlin[Mrows*Hh], g_mix[Mrows*Hh];
__device__ float g_od[MD], g_ema[MD], g_oc[MD];
// bf16 hi/lo split buffers
__device__ __nv_bfloat16 g_xh[MD], g_xl[MD];
__device__ __nv_bfloat16 g_och[MD], g_ocl[MD];
__device__ __nv_bfloat16 g_wth[4*Dm*Dm], g_wtl[4*Dm*Dm];   // transposed [N][K] per matrix

__device__ __forceinline__ float sigm(float x){ return 1.0f/(1.0f+__expf(-x)); }

__device__ __forceinline__ uint32_t smem_u32(const void* p){
    uint32_t a;
    asm("{ .reg .u64 t; cvta.to.shared.u64 t, %1; cvt.u32.u64 %0, t; }" : "=r"(a) : "l"(p));
    return a;
}
__device__ __forceinline__ uint32_t sw128(uint32_t b){ return b ^ ((b >> 3) & 0x70); }

__device__ __forceinline__ void cpa16(uint32_t dst, const void* src){
    asm volatile("cp.async.cg.shared.global [%0], [%1], 16;" :: "r"(dst), "l"(src) : "memory");
}
#define CP_COMMIT() asm volatile("cp.async.commit_group;" ::: "memory")
#define CP_WAIT(n)  asm volatile("cp.async.wait_group %0;" :: "n"(n) : "memory")

#define LDSM_X4(r0,r1,r2,r3, addr) \
    asm volatile("ldmatrix.sync.aligned.m8n8.x4.shared.b16 {%0,%1,%2,%3}, [%4];" \
        : "=r"(r0),"=r"(r1),"=r"(r2),"=r"(r3) : "r"(addr))

#define MMA16816(d, a, b) \
    asm volatile("mma.sync.aligned.m16n8k16.row.col.f32.bf16.bf16.f32 " \
        "{%0,%1,%2,%3}, {%4,%5,%6,%7}, {%8,%9}, {%0,%1,%2,%3};" \
        : "+f"((d)[0]),"+f"((d)[1]),"+f"((d)[2]),"+f"((d)[3]) \
        : "r"((a)[0]),"r"((a)[1]),"r"((a)[2]),"r"((a)[3]), "r"((b)[0]),"r"((b)[1]))

// ================= HMMA GEMM: C[8192,1024] = A[8192,1024] @ W[1024,1024] =========
// A given as hi/lo bf16 [M][K]; W as transposed hi/lo bf16 [N][K].
// 3-MMA bf16 emulation: Ah*Bh + Al*Bh + Ah*Bl (fp32 accumulate).
// Block 128x128, BK=64, 8 warps (4m x 2n), warp tile 32x64. Double-buffered cp.async.
#define TILEB 16384          // one 128x64 bf16 tile, 128B rows
#define STAGEB (4*TILEB)     // Ah, Al, Bh, Bl

__global__ __launch_bounds__(256) void mma_gemm_kernel(
    const __nv_bfloat16* __restrict__ Ah, const __nv_bfloat16* __restrict__ Al,
    const __nv_bfloat16* __restrict__ Bth, const __nv_bfloat16* __restrict__ Btl,
    float* __restrict__ C)
{
    extern __shared__ char dyn[];
    uint32_t raw = smem_u32(dyn);
    uint32_t base = (raw + 1023u) & ~1023u;

    int tid = threadIdx.x, lane = tid & 31, wid = tid >> 5;
    int wm = wid >> 1, wn = wid & 1;
    int m0 = blockIdx.y * 128, n0 = blockIdx.x * 128;

    const __nv_bfloat16* gAh = Ah  + (size_t)m0 * Dm;
    const __nv_bfloat16* gAl = Al  + (size_t)m0 * Dm;
    const __nv_bfloat16* gBh = Bth + (size_t)n0 * Dm;
    const __nv_bfloat16* gBl = Btl + (size_t)n0 * Dm;

    float acc[2][8][4];
#pragma unroll
    for (int f=0; f<2; f++)
#pragma unroll
        for (int j=0; j<8; j++)
#pragma unroll
            for (int e=0; e<4; e++) acc[f][j][e] = 0.0f;

    // precomputed load mapping: 4 chunks of 16B per thread per tile
    int lrow[4], lch[4];
#pragma unroll
    for (int t=0;t<4;t++){ int c = tid + t*256; lrow[t] = c >> 3; lch[t] = c & 7; }

    const int NSTEP = Dm / 64;   // 16

    // prologue: stage 0
    {
        uint32_t sb = base;
#pragma unroll
        for (int t=0;t<4;t++){
            size_t go = (size_t)lrow[t]*Dm + lch[t]*8;
            uint32_t so = sw128((uint32_t)(lrow[t]*128 + lch[t]*16));
            cpa16(sb + so,           gAh + go);
            cpa16(sb + TILEB + so,   gAl + go);
            cpa16(sb + 2*TILEB + so, gBh + go);
            cpa16(sb + 3*TILEB + so, gBl + go);
        }
        CP_COMMIT();
    }

    for (int s = 0; s < NSTEP; s++){
        if (s < NSTEP-1){
            uint32_t sb = base + ((s+1)&1)*STAGEB;
            int k0 = (s+1)*64;
#pragma unroll
            for (int t=0;t<4;t++){
                size_t go = (size_t)lrow[t]*Dm + k0 + lch[t]*8;
                uint32_t so = sw128((uint32_t)(lrow[t]*128 + lch[t]*16));
                cpa16(sb + so,           gAh + go);
                cpa16(sb + TILEB + so,   gAl + go);
                cpa16(sb + 2*TILEB + so, gBh + go);
                cpa16(sb + 3*TILEB + so, gBl + go);
            }
            CP_COMMIT();
            CP_WAIT(1);
        } else {
            CP_WAIT(0);
        }
        __syncthreads();

        uint32_t sb = base + (s&1)*STAGEB;
#pragma unroll
        for (int kk = 0; kk < 4; kk++){
            // A fragments (hi and lo), 2 m16 frags
            uint32_t ah[2][4], al[2][4];
#pragma unroll
            for (int f=0; f<2; f++){
                int arow = wm*32 + f*16 + (lane & 7) + ((lane >> 3) & 1)*8;
                uint32_t ab = sw128((uint32_t)(arow*128 + kk*32 + (lane >> 4)*16));
                LDSM_X4(ah[f][0],ah[f][1],ah[f][2],ah[f][3], sb + ab);
                LDSM_X4(al[f][0],al[f][1],al[f][2],al[f][3], sb + TILEB + ab);
            }
            // B hi fragments: 8 n8 frags via 4 x4 loads
            uint32_t bh[8][2];
#pragma unroll
            for (int g=0; g<4; g++){
                int nrow = wn*64 + g*16 + (lane & 7) + ((lane >> 4) << 3);
                uint32_t bb = sw128((uint32_t)(nrow*128 + kk*32 + ((lane >> 3) & 1)*16));
                uint32_t r0,r1,r2,r3;
                LDSM_X4(r0,r1,r2,r3, sb + 2*TILEB + bb);
                bh[2*g][0]=r0; bh[2*g][1]=r1; bh[2*g+1][0]=r2; bh[2*g+1][1]=r3;
            }
#pragma unroll
            for (int f=0; f<2; f++)
#pragma unroll
                for (int j=0; j<8; j++){
                    MMA16816(acc[f][j], ah[f], bh[j]);
                    MMA16816(acc[f][j], al[f], bh[j]);
                }
            // B lo fragments (reuse regs)
#pragma unroll
            for (int g=0; g<4; g++){
                int nrow = wn*64 + g*16 + (lane & 7) + ((lane >> 4) << 3);
                uint32_t bb = sw128((uint32_t)(nrow*128 + kk*32 + ((lane >> 3) & 1)*16));
                uint32_t r0,r1,r2,r3;
                LDSM_X4(r0,r1,r2,r3, sb + 3*TILEB + bb);
                bh[2*g][0]=r0; bh[2*g][1]=r1; bh[2*g+1][0]=r2; bh[2*g+1][1]=r3;
            }
#pragma unroll
            for (int f=0; f<2; f++)
#pragma unroll
                for (int j=0; j<8; j++)
                    MMA16816(acc[f][j], ah[f], bh[j]);
        }
        __syncthreads();
    }

    // epilogue: direct float2 stores
#pragma unroll
    for (int f=0; f<2; f++){
        int r = m0 + wm*32 + f*16 + (lane >> 2);
#pragma unroll
        for (int j=0; j<8; j++){
            int cc = n0 + wn*64 + j*8 + (lane & 3)*2;
            *(float2*)&C[(size_t)r*Dm + cc]     = make_float2(acc[f][j][0], acc[f][j][1]);
            *(float2*)&C[(size_t)(r+8)*Dm + cc] = make_float2(acc[f][j][2], acc[f][j][3]);
        }
    }
}

// ================= hi/lo split =================
__global__ void split_bf16_kernel(const float* __restrict__ src,
                                  __nv_bfloat16* __restrict__ hi,
                                  __nv_bfloat16* __restrict__ lo, int n)
{
    int i = blockIdx.x * blockDim.x + threadIdx.x;
    if (i < n){
        float x = src[i];
        __nv_bfloat16 h = __float2bfloat16(x);
        hi[i] = h;
        lo[i] = __float2bfloat16(x - __bfloat162float(h));
    }
}

// W [K][N] -> Wt hi/lo [N][K]
__global__ void wsplit_kernel(const float* __restrict__ W,
                              __nv_bfloat16* __restrict__ th,
                              __nv_bfloat16* __restrict__ tl)
{
    __shared__ float tile[32][33];
    int n0 = blockIdx.x * 32, k0 = blockIdx.y * 32;
    int tx = threadIdx.x, ty = threadIdx.y;
    for (int r = ty; r < 32; r += 8) tile[r][tx] = W[(size_t)(k0 + r) * Dm + n0 + tx];
    __syncthreads();
    for (int r = ty; r < 32; r += 8){
        float x = tile[tx][r];
        __nv_bfloat16 h = __float2bfloat16(x);
        th[(size_t)(n0 + r) * Dm + k0 + tx] = h;
        tl[(size_t)(n0 + r) * Dm + k0 + tx] = __float2bfloat16(x - __bfloat162float(h));
    }
}

// ---------------- small projections: beta/gamma/mixlin (smem-cached W) ----------
__global__ __launch_bounds__(256) void proj_small_kernel(const float* __restrict__ X,
                                                         const float* __restrict__ Wb_,
                                                         const float* __restrict__ Wd_,
                                                         const float* __restrict__ Wm_)
{
    __shared__ float4 wb[256], wd[256], wm[256];
    int tid = threadIdx.x, lane = tid & 31, wid = tid >> 5;
    int t = blockIdx.x * 8 + wid;
    float acc[12];
#pragma unroll
    for (int i=0;i<12;i++) acc[i]=0.0f;
    for (int e0 = 0; e0 < 1024; e0 += 256){
        __syncthreads();
        wb[tid] = ((const float4*)Wb_)[e0 + tid];
        wd[tid] = ((const float4*)Wd_)[e0 + tid];
        wm[tid] = ((const float4*)Wm_)[e0 + tid];
        __syncthreads();
        for (int e = lane; e < 256; e += 32){
            float xv = X[(size_t)t*Dm + e0 + e];
            float4 b = wb[e], d = wd[e], m = wm[e];
            acc[0]+=xv*b.x; acc[1]+=xv*b.y; acc[2]+=xv*b.z; acc[3]+=xv*b.w;
            acc[4]+=xv*d.x; acc[5]+=xv*d.y; acc[6]+=xv*d.z; acc[7]+=xv*d.w;
            acc[8]+=xv*m.x; acc[9]+=xv*m.y; acc[10]+=xv*m.z; acc[11]+=xv*m.w;
        }
    }
#pragma unroll
    for (int i=0;i<12;i++){
        float s = acc[i];
        for (int o=16;o;o>>=1) s += __shfl_xor_sync(0xffffffffu, s, o);
        acc[i] = s;
    }
    if (lane == 0){
#pragma unroll
        for (int c=0;c<4;c++){
            g_beta [t*Hh+c] = sigm(acc[c]);
            g_gamma[t*Hh+c] = sigm(acc[4+c]);
            g_mixlin[t*Hh+c] = acc[8+c];
        }
    }
}

// ---------------- depthwise causal conv + silu (optionally double silu) --------
__global__ void conv_silu_kernel(const float* __restrict__ lin, const float* __restrict__ cw,
                                 float* __restrict__ out, int dsilu)
{
    int e = blockIdx.x*blockDim.x + threadIdx.x;
    if (e >= MD) return;
    int t = e / Dm, c = e % Dm;
    int tl = t % Lseq;
    float w0=cw[c*4+0], w1=cw[c*4+1], w2=cw[c*4+2], w3=cw[c*4+3];
    float acc = lin[e]*w3;
    if (tl>=1) acc += lin[e-Dm]*w2;
    if (tl>=2) acc += lin[e-2*Dm]*w1;
    if (tl>=3) acc += lin[e-3*Dm]*w0;
    float y = acc * sigm(acc);
    if (dsilu) y = y * sigm(y);
    out[e] = y;
}

__global__ void conv_mix_kernel(const float* __restrict__ cm, const float* __restrict__ mbias)
{
    int e = blockIdx.x*blockDim.x + threadIdx.x;
    if (e >= Mrows*Hh) return;
    int t = e / Hh, h = e % Hh;
    int tl = t % Lseq;
    float w0=cm[h*4+0], w1=cm[h*4+1], w2=cm[h*4+2], w3=cm[h*4+3];
    float acc = g_mixlin[e]*w3;
    if (tl>=1) acc += g_mixlin[e-Hh]*w2;
    if (tl>=2) acc += g_mixlin[e-2*Hh]*w1;
    if (tl>=3) acc += g_mixlin[e-3*Hh]*w0;
    float y = acc * sigm(acc);             // silu
    g_mix[e] = sigm(y + mbias[h]);
}

// ---------------- per-chunk precompute: l2norm, T (fwd-subst), u, w, A2 --------
__global__ __launch_bounds__(256) void chunk_pre_kernel()
{
    extern __shared__ float sm4[];
    float* sq  = sm4;               // 32*257
    float* skk = sq  + 32*257;      // 32*257
    float* sT  = skk + 32*257;      // 1024
    float* sb  = sT  + 1024;        // 32
    int z = blockIdx.x;
    int b  = z >> 8;
    int h  = (z >> 6) & 3;
    int nc = z & 63;
    int t0 = b*Lseq + nc*CHK;
    int cb = h*DHd;
    int tid = threadIdx.x, lane = tid & 31, wid = tid >> 5;

    for (int e=tid; e<32*256; e+=256){
        int r=e>>8, c=e&255;
        sq [r*257+c] = g_q[(size_t)(t0+r)*Dm + cb + c];
        skk[r*257+c] = g_k[(size_t)(t0+r)*Dm + cb + c];
    }
    if (tid < 32) sb[tid] = g_beta[(t0+tid)*Hh + h];
    __syncthreads();

    for (int r=wid; r<32; r+=8){
        float s=0.0f;
        for (int c=lane;c<256;c+=32){ float v=sq[r*257+c]; s+=v*v; }
        for (int o=16;o;o>>=1) s += __shfl_xor_sync(0xffffffffu,s,o);
        float rn = rsqrtf(s + 1e-6f);
        for (int c=lane;c<256;c+=32){ float v=sq[r*257+c]*rn; sq[r*257+c]=v; g_q[(size_t)(t0+r)*Dm+cb+c]=v; }
        s=0.0f;
        for (int c=lane;c<256;c+=32){ float v=skk[r*257+c]; s+=v*v; }
        for (int o=16;o;o>>=1) s += __shfl_xor_sync(0xffffffffu,s,o);
        rn = rsqrtf(s + 1e-6f);
        for (int c=lane;c<256;c+=32){ float v=skk[r*257+c]*rn; skk[r*257+c]=v; g_k[(size_t)(t0+r)*Dm+cb+c]=v; }
    }
    __syncthreads();

    for (int e=tid; e<1024; e+=256){
        int i=e>>5, j=e&31;
        float val=0.0f;
        if (j < i){
            float s=0.0f;
            for (int p=0;p<256;p++) s += skk[i*257+p]*skk[j*257+p];
            val = -sb[i]*s;
        }
        sT[e]=val;
    }
    __syncthreads();

    if (wid == 0){
        for (int i=1;i<32;i++){
            float a = sT[i*32+lane];
            float acc = 0.0f;
            for (int j=1;j<32;j++){
                float aij = __shfl_sync(0xffffffffu, a, j);
                acc += aij * sT[j*32+lane];
            }
            if (lane < i) sT[i*32+lane] = a + acc;
            __syncwarp();
        }
        sT[lane*32+lane] += 1.0f;
    }
    __syncthreads();

    int abase = z*1024;
    for (int e=tid; e<1024; e+=256){
        int i=e>>5, j=e&31;
        float val=0.0f;
        if (j <= i){
            float s=0.0f;
            for (int p=0;p<256;p++) s += sq[i*257+p]*skk[j*257+p];
            val = s;
        }
        g_A2[abase+e]=val;
    }

    for (int e=tid; e<32*256; e+=256){
        int i=e>>8, c=e&255;
        float uu=0.0f, ww=0.0f;
        for (int j=0;j<32;j++){
            float tb = sT[i*32+j]*sb[j];
            uu += tb * g_v[(size_t)(t0+j)*Dm + cb + c];
            ww += tb * skk[j*257+c];
        }
        g_u[(size_t)(t0+i)*Dm+cb+c]=uu;
        g_w[(size_t)(t0+i)*Dm+cb+c]=ww;
    }
}

// ---------------- sequential inter-chunk recurrence, dv-sliced ----------------
__global__ __launch_bounds__(256) void recurrence_kernel()
{
    extern __shared__ float sm5[];
    float* S   = sm5;             // 256*32
    float* swv = S   + 8192;      // 32*260
    float* sqv = swv + 32*260;
    float* skv = sqv + 32*260;
    float* su  = skv + 32*260;    // 32*32
    float* sA  = su  + 1024;      // 32*32
    float* sua = sA  + 1024;      // 32*32
    float* sR  = sua + 1024;      // 64*32

    int bx = blockIdx.x;
    int bh = bx >> 3, vb = bx & 7;
    int b = bh >> 2, h = bh & 3;
    int cb  = h*DHd;
    int cvb = cb + vb*32;
    int tid = threadIdx.x;
    int tr = tid >> 3, tc = tid & 7;
    const float* Amat = (tr < 16) ? swv : sqv;
    int r0 = (tr & 15)*2;

    for (int i=tid; i<8192; i+=256) S[i]=0.0f;
    __syncthreads();

    for (int ci=0; ci<NCk; ci++){
        int t0 = b*Lseq + ci*CHK;
        for (int e=tid; e<32*256; e+=256){
            int r=e>>8, c=e&255;
            size_t gi = (size_t)(t0+r)*Dm + cb + c;
            swv[r*260+c] = g_w[gi];
            sqv[r*260+c] = g_q[gi];
            skv[r*260+c] = g_k[gi];
        }
        for (int e=tid; e<1024; e+=256){
            int r=e>>5, c=e&31;
            su[e] = g_u[(size_t)(t0+r)*Dm + cvb + c];
            sA[e] = g_A2[(size_t)(bh*NCk+ci)*1024 + e];
        }
        __syncthreads();

        {
            float4 acc0 = make_float4(0,0,0,0), acc1 = acc0;
#pragma unroll 4
            for (int p=0;p<256;p++){
                float a0 = Amat[r0*260+p];
                float a1 = Amat[(r0+1)*260+p];
                float4 sv = *(float4*)&S[p*32 + tc*4];
                acc0.x += a0*sv.x; acc0.y += a0*sv.y; acc0.z += a0*sv.z; acc0.w += a0*sv.w;
                acc1.x += a1*sv.x; acc1.y += a1*sv.y; acc1.z += a1*sv.z; acc1.w += a1*sv.w;
            }
            int rr = tr*2;
            *(float4*)&sR[rr*32     + tc*4] = acc0;
            *(float4*)&sR[(rr+1)*32 + tc*4] = acc1;
        }
        __syncthreads();

        for (int e=tid; e<1024; e+=256) sua[e] = su[e] - sR[e];
        __syncthreads();

        {
            int c = tid & 31, iw = tid >> 5;
#pragma unroll
            for (int rep=0;rep<4;rep++){
                int i = iw + rep*8;
                float o = sR[(32+i)*32 + c];
                for (int j=0;j<32;j++) o += sA[i*32+j]*sua[j*32+c];
                g_od[(size_t)(t0+i)*Dm + cvb + c] = o;
            }
        }

        {
            float4 acc[8];
#pragma unroll
            for (int m=0;m<8;m++) acc[m] = *(float4*)&S[(tr+32*m)*32 + tc*4];
            for (int j=0;j<32;j++){
                float4 b4 = *(float4*)&sua[j*32 + tc*4];
#pragma unroll
                for (int m=0;m<8;m++){
                    float a = skv[j*260 + tr + 32*m];
                    acc[m].x += a*b4.x; acc[m].y += a*b4.y; acc[m].z += a*b4.z; acc[m].w += a*b4.w;
                }
            }
#pragma unroll
            for (int m=0;m<8;m++) *(float4*)&S[(tr+32*m)*32 + tc*4] = acc[m];
        }
        __syncthreads();
    }
}

// ---------------- EMA scan over sequence ----------------
__global__ void ema_kernel()
{
    int bh = blockIdx.x;
    int b = bh >> 2, h = bh & 3;
    int cb = h*DHd;
    int c = threadIdx.x;
    float s = 0.0f;
    for (int t=0;t<Lseq;t++){
        int row = b*Lseq + t;
        float g = g_gamma[row*Hh + h];
        float v = g_v[(size_t)row*Dm + cb + c];
        s = g*s + (1.0f-g)*v;
        g_ema[(size_t)row*Dm + cb + c] = s;
    }
}

// ---------------- mix + rmsnorm ----------------
__global__ __launch_bounds__(256) void combine_kernel(const float* __restrict__ rmsw)
{
    int t = blockIdx.x, c = threadIdx.x;
    __shared__ float red[8];
    for (int h=0;h<Hh;h++){
        float mix = g_mix[t*Hh+h];
        size_t idx = (size_t)t*Dm + h*DHd + c;
        float o = (1.0f-mix)*g_od[idx] + mix*g_ema[idx];
        float s = o*o;
        for (int off=16;off;off>>=1) s += __shfl_xor_sync(0xffffffffu,s,off);
        if ((c&31)==0) red[c>>5]=s;
        __syncthreads();
        float tot = red[0]+red[1]+red[2]+red[3]+red[4]+red[5]+red[6]+red[7];
        float scale = rsqrtf(tot*(1.0f/256.0f) + 1e-5f);
        g_oc[idx] = o*scale*rmsw[c];
        __syncthreads();
    }
}

// ---------------- launcher ----------------
extern "C" void kernel_launch(void* const* d_in, const int* in_sizes, int n_in,
                              void* d_out, int out_size)
{
    const float* X    = (const float*)d_in[0];
    const float* Wq   = (const float*)d_in[1];
    const float* Wk   = (const float*)d_in[2];
    const float* Wv   = (const float*)d_in[3];
    const float* cq   = (const float*)d_in[4];
    const float* ck   = (const float*)d_in[5];
    const float* cv   = (const float*)d_in[6];
    const float* Wb   = (const float*)d_in[7];
    const float* Wdec = (const float*)d_in[8];
    const float* Wmix = (const float*)d_in[9];
    const float* cmix = (const float*)d_in[10];
    const float* mbias= (const float*)d_in[11];
    const float* rmsw = (const float*)d_in[12];
    const float* Wo   = (const float*)d_in[13];
    float* out = (float*)d_out;
    (void)in_sizes; (void)n_in; (void)out_size;

    float *p_qlin,*p_klin,*p_vlin,*p_oc;
    __nv_bfloat16 *p_xh,*p_xl,*p_och,*p_ocl,*p_wth,*p_wtl;
    cudaGetSymbolAddress((void**)&p_qlin, g_qlin);
    cudaGetSymbolAddress((void**)&p_klin, g_klin);
    cudaGetSymbolAddress((void**)&p_vlin, g_vlin);
    cudaGetSymbolAddress((void**)&p_oc,   g_oc);
    cudaGetSymbolAddress((void**)&p_xh,   g_xh);
    cudaGetSymbolAddress((void**)&p_xl,   g_xl);
    cudaGetSymbolAddress((void**)&p_och,  g_och);
    cudaGetSymbolAddress((void**)&p_ocl,  g_ocl);
    cudaGetSymbolAddress((void**)&p_wth,  g_wth);
    cudaGetSymbolAddress((void**)&p_wtl,  g_wtl);

    float *p_q,*p_k,*p_v;
    cudaGetSymbolAddress((void**)&p_q, g_q);
    cudaGetSymbolAddress((void**)&p_k, g_k);
    cudaGetSymbolAddress((void**)&p_v, g_v);

    const int WM = Dm*Dm;
    const int SMEMG = 1024 + 2*STAGEB;   // 132096

    cudaFuncSetAttribute(mma_gemm_kernel, cudaFuncAttributeMaxDynamicSharedMemorySize, SMEMG);

    // hi/lo splits
    split_bf16_kernel<<<(MD+255)/256,256>>>(X, p_xh, p_xl, MD);
    dim3 wg(32,32), wb2(32,8);
    wsplit_kernel<<<wg,wb2>>>(Wq, p_wth + 0*WM, p_wtl + 0*WM);
    wsplit_kernel<<<wg,wb2>>>(Wk, p_wth + 1*WM, p_wtl + 1*WM);
    wsplit_kernel<<<wg,wb2>>>(Wv, p_wth + 2*WM, p_wtl + 2*WM);
    wsplit_kernel<<<wg,wb2>>>(Wo, p_wth + 3*WM, p_wtl + 3*WM);

    dim3 gg(Dm/128, Mrows/128);   // (8, 64)
    mma_gemm_kernel<<<gg,256,SMEMG>>>(p_xh, p_xl, p_wth + 0*WM, p_wtl + 0*WM, p_qlin);
    mma_gemm_kernel<<<gg,256,SMEMG>>>(p_xh, p_xl, p_wth + 1*WM, p_wtl + 1*WM, p_klin);
    mma_gemm_kernel<<<gg,256,SMEMG>>>(p_xh, p_xl, p_wth + 2*WM, p_wtl + 2*WM, p_vlin);

    proj_small_kernel<<<Mrows/8,256>>>(X, Wb, Wdec, Wmix);

    conv_silu_kernel<<<MD/256,256>>>(p_qlin, cq, p_q, 1);
    conv_silu_kernel<<<MD/256,256>>>(p_klin, ck, p_k, 1);
    conv_silu_kernel<<<MD/256,256>>>(p_vlin, cv, p_v, 0);
    conv_mix_kernel<<<(Mrows*Hh+255)/256,256>>>(cmix, mbias);

    const int SMEM4 = (2*(32*257) + 1024 + 32) * 4;
    cudaFuncSetAttribute(chunk_pre_kernel, cudaFuncAttributeMaxDynamicSharedMemorySize, SMEM4);
    chunk_pre_kernel<<<Bb*Hh*NCk, 256, SMEM4>>>();

    const int SMEM5 = (8192 + 3*(32*260) + 3*1024 + 2048) * 4;
    cudaFuncSetAttribute(recurrence_kernel, cudaFuncAttributeMaxDynamicSharedMemorySize, SMEM5);
    recurrence_kernel<<<Bb*Hh*8, 256, SMEM5>>>();

    ema_kernel<<<Bb*Hh, 256>>>();
    combine_kernel<<<Mrows,256>>>(rmsw);

    split_bf16_kernel<<<(MD+255)/256,256>>>(p_oc, p_och, p_ocl, MD);
    mma_gemm_kernel<<<gg,256,SMEMG>>>(p_och, p_ocl, p_wth + 3*WM, p_wtl + 3*WM, out);
}

// round 4
// speedup vs baseline: 1.8930x; 1.3825x over previous
#include <cuda_runtime.h>
#include <cuda_bf16.h>
#include <math.h>
#include <stdint.h>

#define Bb   4
#define Lseq 2048
#define Dm   1024
#define Hh   4
#define DHd  256
#define CHK  32
#define NCk  (Lseq/CHK)      // 64
#define Mrows (Bb*Lseq)      // 8192
#define MD (Mrows*Dm)

// ---------------- scratch (static device globals; no allocation) ----------------
__device__ float g_qlin[MD], g_klin[MD], g_vlin[MD];
__device__ float g_q[MD], g_k[MD], g_v[MD];
__device__ float g_u[MD];
__device__ float g_A2[Bb*Hh*NCk*CHK*CHK];
__device__ float g_beta[Mrows*Hh], g_gamma[Mrows*Hh], g_mixlin[Mrows*Hh], g_mix[Mrows*Hh];
__device__ float g_od[MD], g_ema[MD], g_oc[MD];
// bf16 hi/lo split buffers
__device__ __nv_bfloat16 g_xh[MD], g_xl[MD];
__device__ __nv_bfloat16 g_och[MD], g_ocl[MD];
__device__ __nv_bfloat16 g_wth[4*Dm*Dm], g_wtl[4*Dm*Dm];   // transposed [N][K] per matrix
// recurrence operands (bf16 hi/lo), written by chunk_pre
__device__ __nv_bfloat16 g_wqh[Bb*Hh*NCk*64*256], g_wql[Bb*Hh*NCk*64*256]; // [slot][64][256]
__device__ __nv_bfloat16 g_kth[Bb*Hh*NCk*256*32], g_ktl[Bb*Hh*NCk*256*32]; // [slot][256][32]

__device__ __forceinline__ float sigm(float x){ return 1.0f/(1.0f+__expf(-x)); }

__device__ __forceinline__ uint32_t smem_u32(const void* p){
    uint32_t a;
    asm("{ .reg .u64 t; cvta.to.shared.u64 t, %1; cvt.u32.u64 %0, t; }" : "=r"(a) : "l"(p));
    return a;
}
__device__ __forceinline__ uint32_t sw128(uint32_t b){ return b ^ ((b >> 3) & 0x70); }

__device__ __forceinline__ void cpa16(uint32_t dst, const void* src){
    asm volatile("cp.async.cg.shared.global [%0], [%1], 16;" :: "r"(dst), "l"(src) : "memory");
}
#define CP_COMMIT() asm volatile("cp.async.commit_group;" ::: "memory")
#define CP_WAIT(n)  asm volatile("cp.async.wait_group %0;" :: "n"(n) : "memory")

#define LDSM_X4(r0,r1,r2,r3, addr) \
    asm volatile("ldmatrix.sync.aligned.m8n8.x4.shared.b16 {%0,%1,%2,%3}, [%4];" \
        : "=r"(r0),"=r"(r1),"=r"(r2),"=r"(r3) : "r"(addr))
#define LDSM_X4T(r0,r1,r2,r3, addr) \
    asm volatile("ldmatrix.sync.aligned.m8n8.x4.trans.shared.b16 {%0,%1,%2,%3}, [%4];" \
        : "=r"(r0),"=r"(r1),"=r"(r2),"=r"(r3) : "r"(addr))

#define MMA16816(d, a, b) \
    asm volatile("mma.sync.aligned.m16n8k16.row.col.f32.bf16.bf16.f32 " \
        "{%0,%1,%2,%3}, {%4,%5,%6,%7}, {%8,%9}, {%0,%1,%2,%3};" \
        : "+f"((d)[0]),"+f"((d)[1]),"+f"((d)[2]),"+f"((d)[3]) \
        : "r"((a)[0]),"r"((a)[1]),"r"((a)[2]),"r"((a)[3]), "r"((b)[0]),"r"((b)[1]))

__device__ __forceinline__ void split2(float a, float b, uint32_t &hi, uint32_t &lo){
    __nv_bfloat16 ah = __float2bfloat16(a), bh = __float2bfloat16(b);
    __nv_bfloat16 al = __float2bfloat16(a - __bfloat162float(ah));
    __nv_bfloat16 bl = __float2bfloat16(b - __bfloat162float(bh));
    hi = ((uint32_t)__bfloat16_as_ushort(bh) << 16) | (uint32_t)__bfloat16_as_ushort(ah);
    lo = ((uint32_t)__bfloat16_as_ushort(bl) << 16) | (uint32_t)__bfloat16_as_ushort(al);
}

// ================= HMMA GEMM v2: 128x64 tile, BK=64, 2 stages, 2 CTA/SM =========
#define TILEA2 16384   // 128x64 bf16 (128B rows)
#define TILEB2 8192    // 64x64 bf16
#define STAGE2 (2*TILEA2 + 2*TILEB2)   // 49152

__global__ __launch_bounds__(256,2) void mma_gemm_kernel(
    const __nv_bfloat16* __restrict__ Ah, const __nv_bfloat16* __restrict__ Al,
    const __nv_bfloat16* __restrict__ Bth, const __nv_bfloat16* __restrict__ Btl,
    float* __restrict__ C)
{
    extern __shared__ char dyn[];
    uint32_t raw = smem_u32(dyn);
    uint32_t base = (raw + 127u) & ~127u;

    int tid = threadIdx.x, lane = tid & 31, wid = tid >> 5;
    int wm = wid >> 1, wn = wid & 1;
    int m0 = blockIdx.y * 128, n0 = blockIdx.x * 64;

    const __nv_bfloat16* gAh = Ah  + (size_t)m0 * Dm;
    const __nv_bfloat16* gAl = Al  + (size_t)m0 * Dm;
    const __nv_bfloat16* gBh = Bth + (size_t)n0 * Dm;
    const __nv_bfloat16* gBl = Btl + (size_t)n0 * Dm;

    float acc[2][4][4];
#pragma unroll
    for (int f=0; f<2; f++)
#pragma unroll
        for (int j=0; j<4; j++)
#pragma unroll
            for (int e=0; e<4; e++) acc[f][j][e] = 0.0f;

    // prologue stage 0
    {
        uint32_t sb = base;
#pragma unroll
        for (int t=0;t<4;t++){
            int c = tid + t*256;
            int row = c >> 3, col = c & 7;
            size_t go = (size_t)row*Dm + col*8;
            uint32_t so = sw128((uint32_t)(row*128 + col*16));
            cpa16(sb + so,          gAh + go);
            cpa16(sb + TILEA2 + so, gAl + go);
        }
#pragma unroll
        for (int t=0;t<2;t++){
            int c = tid + t*256;
            int row = c >> 3, col = c & 7;
            size_t go = (size_t)row*Dm + col*8;
            uint32_t so = sw128((uint32_t)(row*128 + col*16));
            cpa16(sb + 2*TILEA2 + so,          gBh + go);
            cpa16(sb + 2*TILEA2 + TILEB2 + so, gBl + go);
        }
        CP_COMMIT();
    }

    const int NSTEP = Dm / 64;   // 16
    for (int s = 0; s < NSTEP; s++){
        if (s < NSTEP-1){
            uint32_t sb = base + ((s+1)&1)*STAGE2;
            int k0 = (s+1)*64;
#pragma unroll
            for (int t=0;t<4;t++){
                int c = tid + t*256;
                int row = c >> 3, col = c & 7;
                size_t go = (size_t)row*Dm + k0 + col*8;
                uint32_t so = sw128((uint32_t)(row*128 + col*16));
                cpa16(sb + so,          gAh + go);
                cpa16(sb + TILEA2 + so, gAl + go);
            }
#pragma unroll
            for (int t=0;t<2;t++){
                int c = tid + t*256;
                int row = c >> 3, col = c & 7;
                size_t go = (size_t)row*Dm + k0 + col*8;
                uint32_t so = sw128((uint32_t)(row*128 + col*16));
                cpa16(sb + 2*TILEA2 + so,          gBh + go);
                cpa16(sb + 2*TILEA2 + TILEB2 + so, gBl + go);
            }
            CP_COMMIT();
            CP_WAIT(1);
        } else {
            CP_WAIT(0);
        }
        __syncthreads();

        uint32_t sb = base + (s&1)*STAGE2;
#pragma unroll
        for (int kk = 0; kk < 4; kk++){
            uint32_t ah[2][4], al[2][4];
#pragma unroll
            for (int f=0; f<2; f++){
                int arow = wm*32 + f*16 + (lane & 7) + ((lane >> 3) & 1)*8;
                uint32_t ab = sw128((uint32_t)(arow*128 + kk*32 + (lane >> 4)*16));
                LDSM_X4(ah[f][0],ah[f][1],ah[f][2],ah[f][3], sb + ab);
                LDSM_X4(al[f][0],al[f][1],al[f][2],al[f][3], sb + TILEA2 + ab);
            }
            uint32_t bfrag[4][2];
#pragma unroll
            for (int g=0; g<2; g++){
                int nrow = wn*32 + g*16 + (lane & 7) + ((lane >> 4) << 3);
                uint32_t bb = sw128((uint32_t)(nrow*128 + kk*32 + ((lane >> 3) & 1)*16));
                uint32_t r0,r1,r2,r3;
                LDSM_X4(r0,r1,r2,r3, sb + 2*TILEA2 + bb);
                bfrag[2*g][0]=r0; bfrag[2*g][1]=r1; bfrag[2*g+1][0]=r2; bfrag[2*g+1][1]=r3;
            }
#pragma unroll
            for (int f=0; f<2; f++)
#pragma unroll
                for (int j=0; j<4; j++){
                    MMA16816(acc[f][j], ah[f], bfrag[j]);
                    MMA16816(acc[f][j], al[f], bfrag[j]);
                }
#pragma unroll
            for (int g=0; g<2; g++){
                int nrow = wn*32 + g*16 + (lane & 7) + ((lane >> 4) << 3);
                uint32_t bb = sw128((uint32_t)(nrow*128 + kk*32 + ((lane >> 3) & 1)*16));
                uint32_t r0,r1,r2,r3;
                LDSM_X4(r0,r1,r2,r3, sb + 2*TILEA2 + TILEB2 + bb);
                bfrag[2*g][0]=r0; bfrag[2*g][1]=r1; bfrag[2*g+1][0]=r2; bfrag[2*g+1][1]=r3;
            }
#pragma unroll
            for (int f=0; f<2; f++)
#pragma unroll
                for (int j=0; j<4; j++)
                    MMA16816(acc[f][j], ah[f], bfrag[j]);
        }
        __syncthreads();
    }

#pragma unroll
    for (int f=0; f<2; f++){
        int r = m0 + wm*32 + f*16 + (lane >> 2);
#pragma unroll
        for (int j=0; j<4; j++){
            int cc = n0 + wn*32 + j*8 + (lane & 3)*2;
            *(float2*)&C[(size_t)r*Dm + cc]     = make_float2(acc[f][j][0], acc[f][j][1]);
            *(float2*)&C[(size_t)(r+8)*Dm + cc] = make_float2(acc[f][j][2], acc[f][j][3]);
        }
    }
}

// ================= hi/lo split =================
__global__ void split_bf16_kernel(const float* __restrict__ src,
                                  __nv_bfloat16* __restrict__ hi,
                                  __nv_bfloat16* __restrict__ lo, int n)
{
    int i = blockIdx.x * blockDim.x + threadIdx.x;
    if (i < n){
        float x = src[i];
        __nv_bfloat16 h = __float2bfloat16(x);
        hi[i] = h;
        lo[i] = __float2bfloat16(x - __bfloat162float(h));
    }
}

// W [K][N] -> Wt hi/lo [N][K]
__global__ void wsplit_kernel(const float* __restrict__ W,
                              __nv_bfloat16* __restrict__ th,
                              __nv_bfloat16* __restrict__ tl)
{
    __shared__ float tile[32][33];
    int n0 = blockIdx.x * 32, k0 = blockIdx.y * 32;
    int tx = threadIdx.x, ty = threadIdx.y;
    for (int r = ty; r < 32; r += 8) tile[r][tx] = W[(size_t)(k0 + r) * Dm + n0 + tx];
    __syncthreads();
    for (int r = ty; r < 32; r += 8){
        float x = tile[tx][r];
        __nv_bfloat16 h = __float2bfloat16(x);
        th[(size_t)(n0 + r) * Dm + k0 + tx] = h;
        tl[(size_t)(n0 + r) * Dm + k0 + tx] = __float2bfloat16(x - __bfloat162float(h));
    }
}

// ---------------- small projections ----------------
__global__ __launch_bounds__(256) void proj_small_kernel(const float* __restrict__ X,
                                                         const float* __restrict__ Wb_,
                                                         const float* __restrict__ Wd_,
                                                         const float* __restrict__ Wm_)
{
    __shared__ float4 wb[256], wd[256], wm[256];
    int tid = threadIdx.x, lane = tid & 31, wid = tid >> 5;
    int t = blockIdx.x * 8 + wid;
    float acc[12];
#pragma unroll
    for (int i=0;i<12;i++) acc[i]=0.0f;
    for (int e0 = 0; e0 < 1024; e0 += 256){
        __syncthreads();
        wb[tid] = ((const float4*)Wb_)[e0 + tid];
        wd[tid] = ((const float4*)Wd_)[e0 + tid];
        wm[tid] = ((const float4*)Wm_)[e0 + tid];
        __syncthreads();
        for (int e = lane; e < 256; e += 32){
            float xv = X[(size_t)t*Dm + e0 + e];
            float4 b = wb[e], d = wd[e], m = wm[e];
            acc[0]+=xv*b.x; acc[1]+=xv*b.y; acc[2]+=xv*b.z; acc[3]+=xv*b.w;
            acc[4]+=xv*d.x; acc[5]+=xv*d.y; acc[6]+=xv*d.z; acc[7]+=xv*d.w;
            acc[8]+=xv*m.x; acc[9]+=xv*m.y; acc[10]+=xv*m.z; acc[11]+=xv*m.w;
        }
    }
#pragma unroll
    for (int i=0;i<12;i++){
        float s = acc[i];
        for (int o=16;o;o>>=1) s += __shfl_xor_sync(0xffffffffu, s, o);
        acc[i] = s;
    }
    if (lane == 0){
#pragma unroll
        for (int c=0;c<4;c++){
            g_beta [t*Hh+c] = sigm(acc[c]);
            g_gamma[t*Hh+c] = sigm(acc[4+c]);
            g_mixlin[t*Hh+c] = acc[8+c];
        }
    }
}

// ---------------- depthwise causal conv + silu --------
__global__ void conv_silu_kernel(const float* __restrict__ lin, const float* __restrict__ cw,
                                 float* __restrict__ out, int dsilu)
{
    int e = blockIdx.x*blockDim.x + threadIdx.x;
    if (e >= MD) return;
    int t = e / Dm, c = e % Dm;
    int tl = t % Lseq;
    float w0=cw[c*4+0], w1=cw[c*4+1], w2=cw[c*4+2], w3=cw[c*4+3];
    float acc = lin[e]*w3;
    if (tl>=1) acc += lin[e-Dm]*w2;
    if (tl>=2) acc += lin[e-2*Dm]*w1;
    if (tl>=3) acc += lin[e-3*Dm]*w0;
    float y = acc * sigm(acc);
    if (dsilu) y = y * sigm(y);
    out[e] = y;
}

__global__ void conv_mix_kernel(const float* __restrict__ cm, const float* __restrict__ mbias)
{
    int e = blockIdx.x*blockDim.x + threadIdx.x;
    if (e >= Mrows*Hh) return;
    int t = e / Hh, h = e % Hh;
    int tl = t % Lseq;
    float w0=cm[h*4+0], w1=cm[h*4+1], w2=cm[h*4+2], w3=cm[h*4+3];
    float acc = g_mixlin[e]*w3;
    if (tl>=1) acc += g_mixlin[e-Hh]*w2;
    if (tl>=2) acc += g_mixlin[e-2*Hh]*w1;
    if (tl>=3) acc += g_mixlin[e-3*Hh]*w0;
    float y = acc * sigm(acc);
    g_mix[e] = sigm(y + mbias[h]);
}

// ---------------- per-chunk precompute ----------------
__global__ __launch_bounds__(256) void chunk_pre_kernel()
{
    extern __shared__ float sm4[];
    float* sq  = sm4;               // 32*257
    float* skk = sq  + 32*257;      // 32*257
    float* sT  = skk + 32*257;      // 1024
    float* sb  = sT  + 1024;        // 32
    int z = blockIdx.x;
    int b  = z >> 8;
    int h  = (z >> 6) & 3;
    int nc = z & 63;
    int t0 = b*Lseq + nc*CHK;
    int cb = h*DHd;
    int tid = threadIdx.x, lane = tid & 31, wid = tid >> 5;

    for (int e=tid; e<32*256; e+=256){
        int r=e>>8, c=e&255;
        sq [r*257+c] = g_q[(size_t)(t0+r)*Dm + cb + c];
        skk[r*257+c] = g_k[(size_t)(t0+r)*Dm + cb + c];
    }
    if (tid < 32) sb[tid] = g_beta[(t0+tid)*Hh + h];
    __syncthreads();

    for (int r=wid; r<32; r+=8){
        float s=0.0f;
        for (int c=lane;c<256;c+=32){ float v=sq[r*257+c]; s+=v*v; }
        for (int o=16;o;o>>=1) s += __shfl_xor_sync(0xffffffffu,s,o);
        float rn = rsqrtf(s + 1e-6f);
        for (int c=lane;c<256;c+=32){ sq[r*257+c] *= rn; }
        s=0.0f;
        for (int c=lane;c<256;c+=32){ float v=skk[r*257+c]; s+=v*v; }
        for (int o=16;o;o>>=1) s += __shfl_xor_sync(0xffffffffu,s,o);
        rn = rsqrtf(s + 1e-6f);
        for (int c=lane;c<256;c+=32){ skk[r*257+c] *= rn; }
    }
    __syncthreads();

    for (int e=tid; e<1024; e+=256){
        int i=e>>5, j=e&31;
        float val=0.0f;
        if (j < i){
            float s=0.0f;
            for (int p=0;p<256;p++) s += skk[i*257+p]*skk[j*257+p];
            val = -sb[i]*s;
        }
        sT[e]=val;
    }
    __syncthreads();

    if (wid == 0){
        for (int i=1;i<32;i++){
            float a = sT[i*32+lane];
            float acc = 0.0f;
            for (int j=1;j<32;j++){
                float aij = __shfl_sync(0xffffffffu, a, j);
                acc += aij * sT[j*32+lane];
            }
            if (lane < i) sT[i*32+lane] = a + acc;
            __syncwarp();
        }
        sT[lane*32+lane] += 1.0f;
    }
    __syncthreads();

    size_t abase = (size_t)z*1024;
    for (int e=tid; e<1024; e+=256){
        int i=e>>5, j=e&31;
        float val=0.0f;
        if (j <= i){
            float s=0.0f;
            for (int p=0;p<256;p++) s += sq[i*257+p]*skk[j*257+p];
            val = s;
        }
        g_A2[abase+e]=val;
    }

    // u = T@(v*beta) -> fp32; w = T@(k*beta) -> WQ rows 0-31 (bf16 hi/lo)
    size_t wqb = (size_t)z*16384;
    for (int e=tid; e<32*256; e+=256){
        int i=e>>8, c=e&255;
        float uu=0.0f, ww=0.0f;
        for (int j=0;j<32;j++){
            float tb = sT[i*32+j]*sb[j];
            uu += tb * g_v[(size_t)(t0+j)*Dm + cb + c];
            ww += tb * skk[j*257+c];
        }
        g_u[(size_t)(t0+i)*Dm+cb+c]=uu;
        __nv_bfloat16 wh = __float2bfloat16(ww);
        g_wqh[wqb + i*256 + c] = wh;
        g_wql[wqb + i*256 + c] = __float2bfloat16(ww - __bfloat162float(wh));
        // q -> WQ rows 32-63
        float qv = sq[i*257+c];
        __nv_bfloat16 qh = __float2bfloat16(qv);
        g_wqh[wqb + (32+i)*256 + c] = qh;
        g_wql[wqb + (32+i)*256 + c] = __float2bfloat16(qv - __bfloat162float(qh));
    }
    // k^T hi/lo [256][32]
    size_t ktb = (size_t)z*8192;
    for (int e=tid; e<8192; e+=256){
        int r=e>>5, j=e&31;
        float kv = skk[j*257 + r];
        __nv_bfloat16 kh = __float2bfloat16(kv);
        g_kth[ktb + r*32 + j] = kh;
        g_ktl[ktb + r*32 + j] = __float2bfloat16(kv - __bfloat162float(kh));
    }
}

// ---------------- MMA recurrence, dv-sliced ----------------
// grid = 128 (b,h,vb), 256 threads. S persistent in register fragments.
__global__ __launch_bounds__(256) void recurrence_kernel()
{
    extern __shared__ char sm5[];
    uint32_t raw = smem_u32(sm5);
    uint32_t base = (raw + 127u) & ~127u;
    char* p0 = sm5 + (base - raw);

    const uint32_t oWQh = 0, oWQl = 32768, oSh = 65536, oSl = 86016;
    const uint32_t oKTh = 106496, oKTl = 126976, oUAh = 147456, oUAl = 150016;
    const uint32_t oU = 152576, oA2 = 157184, oRq = 161792, oUA32 = 166400;

    uint32_t uWQh = base+oWQh, uWQl = base+oWQl, uSh = base+oSh, uSl = base+oSl;
    uint32_t uKTh = base+oKTh, uKTl = base+oKTl, uUAh = base+oUAh, uUAl = base+oUAl;
    float* u_s  = (float*)(p0 + oU);
    float* A2_s = (float*)(p0 + oA2);
    float* Rq_s = (float*)(p0 + oRq);
    float* ua_s = (float*)(p0 + oUA32);
    char* pSh = p0 + oSh; char* pSl = p0 + oSl;
    char* pUAh = p0 + oUAh; char* pUAl = p0 + oUAl;

    int bx = blockIdx.x;
    int bh = bx >> 3, vb = bx & 7;
    int b = bh >> 2, h = bx >> 3 & 3;
    int cvb = h*DHd + vb*32;
    int tid = threadIdx.x, lane = tid & 31, wid = tid >> 5;
    int rm = wid >> 1, rn = wid & 1;

    float accS[2][4][4];
#pragma unroll
    for (int tm=0;tm<2;tm++)
#pragma unroll
        for (int tn=0;tn<4;tn++)
#pragma unroll
            for (int e=0;e<4;e++) accS[tm][tn][e]=0.0f;

    for (int ci=0; ci<NCk; ci++){
        __syncthreads();
        int slot = bh*NCk + ci;
        int t0 = b*Lseq + ci*CHK;
        const __nv_bfloat16* gwqh = g_wqh + (size_t)slot*16384;
        const __nv_bfloat16* gwql = g_wql + (size_t)slot*16384;
        const __nv_bfloat16* gkth = g_kth + (size_t)slot*8192;
        const __nv_bfloat16* gktl = g_ktl + (size_t)slot*8192;

        // P0: async loads
#pragma unroll
        for (int t=0;t<8;t++){
            int c = tid + t*256;
            int row = c >> 5, col = c & 31;
            uint32_t dst = row*512 + ((uint32_t)(col ^ (row & 7)) << 4);
            cpa16(uWQh + dst, gwqh + c*8);
            cpa16(uWQl + dst, gwql + c*8);
        }
#pragma unroll
        for (int t=0;t<4;t++){
            int c = tid + t*256;
            int row = c >> 2, col = c & 3;
            uint32_t dst = row*80 + (col << 4);
            cpa16(uKTh + dst, gkth + c*8);
            cpa16(uKTl + dst, gktl + c*8);
        }
        {
            int row = tid >> 3, col = tid & 7;
            cpa16(base + oU + row*144 + col*16, &g_u[(size_t)(t0+row)*Dm + cvb + col*4]);
            cpa16(base + oA2 + row*144 + col*16, g_A2 + (size_t)slot*1024 + tid*4);
        }
        CP_COMMIT();

        // P6: convert persistent S fragments -> Sh/Sl (bf16 [256dk][80B rows, 64B data])
#pragma unroll
        for (int tm=0;tm<2;tm++)
#pragma unroll
        for (int tn=0;tn<4;tn++){
            int r = wid*32 + tm*16 + (lane>>2);
            int c = tn*8 + (lane&3)*2;
            uint32_t hw, lw;
            split2(accS[tm][tn][0], accS[tm][tn][1], hw, lw);
            *(uint32_t*)(pSh + r*80 + c*2) = hw;
            *(uint32_t*)(pSl + r*80 + c*2) = lw;
            split2(accS[tm][tn][2], accS[tm][tn][3], hw, lw);
            *(uint32_t*)(pSh + (r+8)*80 + c*2) = hw;
            *(uint32_t*)(pSl + (r+8)*80 + c*2) = lw;
        }

        CP_WAIT(0);
        __syncthreads();

        // P2: R = [W;Q] @ S  (m64 n32 k256)
        float accR[2][4];
#pragma unroll
        for (int j=0;j<2;j++)
#pragma unroll
            for (int e=0;e<4;e++) accR[j][e]=0.0f;

#pragma unroll 4
        for (int kk=0; kk<16; kk++){
            int arow = rm*16 + (lane & 7) + ((lane >> 3) & 1)*8;
            int achunk = kk*2 + (lane >> 4);
            uint32_t aoff = arow*512 + ((uint32_t)(achunk ^ (arow & 7)) << 4);
            uint32_t ah[4], al[4];
            LDSM_X4(ah[0],ah[1],ah[2],ah[3], uWQh + aoff);
            LDSM_X4(al[0],al[1],al[2],al[3], uWQl + aoff);

            int krow = kk*16 + (lane & 7) + ((lane >> 3) & 1)*8;
            uint32_t boff = krow*80 + rn*32 + ((lane >> 4) << 4);
            uint32_t s0,s1,s2,s3;
            LDSM_X4T(s0,s1,s2,s3, uSh + boff);
            uint32_t bh0[2] = {s0,s1}, bh1[2] = {s2,s3};
            LDSM_X4T(s0,s1,s2,s3, uSl + boff);
            uint32_t bl0[2] = {s0,s1}, bl1[2] = {s2,s3};

            MMA16816(accR[0], ah, bh0);
            MMA16816(accR[0], al, bh0);
            MMA16816(accR[0], ah, bl0);
            MMA16816(accR[1], ah, bh1);
            MMA16816(accR[1], al, bh1);
            MMA16816(accR[1], ah, bl1);
        }

        // P3: u_adj (warps 0-3) / Rq (warps 4-7)
        if (wid < 4){
#pragma unroll
            for (int j=0;j<2;j++){
                int c = rn*16 + j*8 + (lane&3)*2;
                int r1 = rm*16 + (lane>>2);
                float ua0 = u_s[r1*36+c]   - accR[j][0];
                float ua1 = u_s[r1*36+c+1] - accR[j][1];
                uint32_t hw, lw;
                split2(ua0, ua1, hw, lw);
                *(uint32_t*)(pUAh + r1*80 + c*2) = hw;
                *(uint32_t*)(pUAl + r1*80 + c*2) = lw;
                *(float2*)&ua_s[r1*36+c] = make_float2(ua0, ua1);
                float ua2 = u_s[(r1+8)*36+c]   - accR[j][2];
                float ua3 = u_s[(r1+8)*36+c+1] - accR[j][3];
                split2(ua2, ua3, hw, lw);
                *(uint32_t*)(pUAh + (r1+8)*80 + c*2) = hw;
                *(uint32_t*)(pUAl + (r1+8)*80 + c*2) = lw;
                *(float2*)&ua_s[(r1+8)*36+c] = make_float2(ua2, ua3);
            }
        } else {
#pragma unroll
            for (int j=0;j<2;j++){
                int c = rn*16 + j*8 + (lane&3)*2;
                int r1 = (rm-2)*16 + (lane>>2);
                *(float2*)&Rq_s[r1*36+c]     = make_float2(accR[j][0], accR[j][1]);
                *(float2*)&Rq_s[(r1+8)*36+c] = make_float2(accR[j][2], accR[j][3]);
            }
        }
        __syncthreads();

        // P4: o = Q@S + A2 @ u_adj -> global
        {
            int c = tid & 31, rb = tid >> 5;
            float o0 = Rq_s[rb*36+c], o1 = Rq_s[(rb+8)*36+c];
            float o2 = Rq_s[(rb+16)*36+c], o3 = Rq_s[(rb+24)*36+c];
#pragma unroll 8
            for (int j=0;j<32;j++){
                float uv = ua_s[j*36+c];
                o0 += A2_s[rb*36+j]*uv;
                o1 += A2_s[(rb+8)*36+j]*uv;
                o2 += A2_s[(rb+16)*36+j]*uv;
                o3 += A2_s[(rb+24)*36+j]*uv;
            }
            g_od[(size_t)(t0+rb)*Dm + cvb + c]      = o0;
            g_od[(size_t)(t0+rb+8)*Dm + cvb + c]    = o1;
            g_od[(size_t)(t0+rb+16)*Dm + cvb + c]   = o2;
            g_od[(size_t)(t0+rb+24)*Dm + cvb + c]   = o3;
        }

        // P5: S += K^T @ u_adj  (m256 n32 k32), warp owns dk rows wid*32..+31
#pragma unroll
        for (int kk=0; kk<2; kk++){
            uint32_t a_h[2][4], a_l[2][4];
#pragma unroll
            for (int tm=0;tm<2;tm++){
                int mrow = wid*32 + tm*16 + (lane & 7) + ((lane >> 3) & 1)*8;
                uint32_t aoff = mrow*80 + kk*32 + ((lane >> 4) << 4);
                LDSM_X4(a_h[tm][0],a_h[tm][1],a_h[tm][2],a_h[tm][3], uKTh + aoff);
                LDSM_X4(a_l[tm][0],a_l[tm][1],a_l[tm][2],a_l[tm][3], uKTl + aoff);
            }
            uint32_t bu_h[4][2], bu_l[4][2];
#pragma unroll
            for (int g=0; g<2; g++){
                int krow = kk*16 + (lane & 7) + ((lane >> 3) & 1)*8;
                uint32_t boff = krow*80 + g*32 + ((lane >> 4) << 4);
                uint32_t r0,r1,r2,r3;
                LDSM_X4T(r0,r1,r2,r3, uUAh + boff);
                bu_h[2*g][0]=r0; bu_h[2*g][1]=r1; bu_h[2*g+1][0]=r2; bu_h[2*g+1][1]=r3;
                LDSM_X4T(r0,r1,r2,r3, uUAl + boff);
                bu_l[2*g][0]=r0; bu_l[2*g][1]=r1; bu_l[2*g+1][0]=r2; bu_l[2*g+1][1]=r3;
            }
#pragma unroll
            for (int tm=0;tm<2;tm++)
#pragma unroll
                for (int tn=0;tn<4;tn++){
                    MMA16816(accS[tm][tn], a_h[tm], bu_h[tn]);
                    MMA16816(accS[tm][tn], a_l[tm], bu_h[tn]);
                    MMA16816(accS[tm][tn], a_h[tm], bu_l[tn]);
                }
        }
    }
}

// ---------------- EMA scan over sequence ----------------
__global__ void ema_kernel()
{
    int bh = blockIdx.x;
    int b = bh >> 2, h = bh & 3;
    int cb = h*DHd;
    int c = threadIdx.x;
    float s = 0.0f;
    for (int t=0;t<Lseq;t++){
        int row = b*Lseq + t;
        float g = g_gamma[row*Hh + h];
        float v = g_v[(size_t)row*Dm + cb + c];
        s = g*s + (1.0f-g)*v;
        g_ema[(size_t)row*Dm + cb + c] = s;
    }
}

// ---------------- mix + rmsnorm ----------------
__global__ __launch_bounds__(256) void combine_kernel(const float* __restrict__ rmsw)
{
    int t = blockIdx.x, c = threadIdx.x;
    __shared__ float red[8];
    for (int h=0;h<Hh;h++){
        float mix = g_mix[t*Hh+h];
        size_t idx = (size_t)t*Dm + h*DHd + c;
        float o = (1.0f-mix)*g_od[idx] + mix*g_ema[idx];
        float s = o*o;
        for (int off=16;off;off>>=1) s += __shfl_xor_sync(0xffffffffu,s,off);
        if ((c&31)==0) red[c>>5]=s;
        __syncthreads();
        float tot = red[0]+red[1]+red[2]+red[3]+red[4]+red[5]+red[6]+red[7];
        float scale = rsqrtf(tot*(1.0f/256.0f) + 1e-5f);
        g_oc[idx] = o*scale*rmsw[c];
        __syncthreads();
    }
}

// ---------------- launcher ----------------
extern "C" void kernel_launch(void* const* d_in, const int* in_sizes, int n_in,
                              void* d_out, int out_size)
{
    const float* X    = (const float*)d_in[0];
    const float* Wq   = (const float*)d_in[1];
    const float* Wk   = (const float*)d_in[2];
    const float* Wv   = (const float*)d_in[3];
    const float* cq   = (const float*)d_in[4];
    const float* ck   = (const float*)d_in[5];
    const float* cv   = (const float*)d_in[6];
    const float* Wb   = (const float*)d_in[7];
    const float* Wdec = (const float*)d_in[8];
    const float* Wmix = (const float*)d_in[9];
    const float* cmix = (const float*)d_in[10];
    const float* mbias= (const float*)d_in[11];
    const float* rmsw = (const float*)d_in[12];
    const float* Wo   = (const float*)d_in[13];
    float* out = (float*)d_out;
    (void)in_sizes; (void)n_in; (void)out_size;

    float *p_qlin,*p_klin,*p_vlin,*p_oc,*p_q,*p_k,*p_v;
    __nv_bfloat16 *p_xh,*p_xl,*p_och,*p_ocl,*p_wth,*p_wtl;
    cudaGetSymbolAddress((void**)&p_qlin, g_qlin);
    cudaGetSymbolAddress((void**)&p_klin, g_klin);
    cudaGetSymbolAddress((void**)&p_vlin, g_vlin);
    cudaGetSymbolAddress((void**)&p_oc,   g_oc);
    cudaGetSymbolAddress((void**)&p_xh,   g_xh);
    cudaGetSymbolAddress((void**)&p_xl,   g_xl);
    cudaGetSymbolAddress((void**)&p_och,  g_och);
    cudaGetSymbolAddress((void**)&p_ocl,  g_ocl);
    cudaGetSymbolAddress((void**)&p_wth,  g_wth);
    cudaGetSymbolAddress((void**)&p_wtl,  g_wtl);
    cudaGetSymbolAddress((void**)&p_q, g_q);
    cudaGetSymbolAddress((void**)&p_k, g_k);
    cudaGetSymbolAddress((void**)&p_v, g_v);

    const int WM = Dm*Dm;
    const int SMEMG = 2*STAGE2 + 256;      // ~98.5KB

    cudaFuncSetAttribute(mma_gemm_kernel, cudaFuncAttributeMaxDynamicSharedMemorySize, SMEMG);

    split_bf16_kernel<<<(MD+255)/256,256>>>(X, p_xh, p_xl, MD);
    dim3 wg(32,32), wb2(32,8);
    wsplit_kernel<<<wg,wb2>>>(Wq, p_wth + 0*WM, p_wtl + 0*WM);
    wsplit_kernel<<<wg,wb2>>>(Wk, p_wth + 1*WM, p_wtl + 1*WM);
    wsplit_kernel<<<wg,wb2>>>(Wv, p_wth + 2*WM, p_wtl + 2*WM);
    wsplit_kernel<<<wg,wb2>>>(Wo, p_wth + 3*WM, p_wtl + 3*WM);

    dim3 gg(Dm/64, Mrows/128);   // (16, 64)
    mma_gemm_kernel<<<gg,256,SMEMG>>>(p_xh, p_xl, p_wth + 0*WM, p_wtl + 0*WM, p_qlin);
    mma_gemm_kernel<<<gg,256,SMEMG>>>(p_xh, p_xl, p_wth + 1*WM, p_wtl + 1*WM, p_klin);
    mma_gemm_kernel<<<gg,256,SMEMG>>>(p_xh, p_xl, p_wth + 2*WM, p_wtl + 2*WM, p_vlin);

    proj_small_kernel<<<Mrows/8,256>>>(X, Wb, Wdec, Wmix);

    conv_silu_kernel<<<MD/256,256>>>(p_qlin, cq, p_q, 1);
    conv_silu_kernel<<<MD/256,256>>>(p_klin, ck, p_k, 1);
    conv_silu_kernel<<<MD/256,256>>>(p_vlin, cv, p_v, 0);
    conv_mix_kernel<<<(Mrows*Hh+255)/256,256>>>(cmix, mbias);

    const int SMEM4 = (2*(32*257) + 1024 + 32) * 4;
    cudaFuncSetAttribute(chunk_pre_kernel, cudaFuncAttributeMaxDynamicSharedMemorySize, SMEM4);
    chunk_pre_kernel<<<Bb*Hh*NCk, 256, SMEM4>>>();

    const int SMEM5 = 171008 + 256;
    cudaFuncSetAttribute(recurrence_kernel, cudaFuncAttributeMaxDynamicSharedMemorySize, SMEM5);
    recurrence_kernel<<<Bb*Hh*8, 256, SMEM5>>>();

    ema_kernel<<<Bb*Hh, 256>>>();
    combine_kernel<<<Mrows,256>>>(rmsw);

    split_bf16_kernel<<<(MD+255)/256,256>>>(p_oc, p_och, p_ocl, MD);
    mma_gemm_kernel<<<gg,256,SMEMG>>>(p_och, p_ocl, p_wth + 3*WM, p_wtl + 3*WM, out);
}

// round 5
// speedup vs baseline: 3.6319x; 1.9186x over previous
#include <cuda_runtime.h>
#include <cuda_bf16.h>
#include <math.h>
#include <stdint.h>

#define Bb   4
#define Lseq 2048
#define Dm   1024
#define Hh   4
#define DHd  256
#define CHK  32
#define NCk  (Lseq/CHK)      // 64
#define Mrows (Bb*Lseq)      // 8192
#define MD (Mrows*Dm)

// ---------------- scratch ----------------
__device__ float g_qlin[MD], g_klin[MD], g_vlin[MD];
__device__ float g_q[MD], g_k[MD], g_v[MD];
__device__ float g_u[MD];
__device__ float g_A2[Bb*Hh*NCk*CHK*CHK];
__device__ float g_beta[Mrows*Hh], g_gamma[Mrows*Hh], g_mixlin[Mrows*Hh], g_mix[Mrows*Hh];
__device__ float g_od[MD], g_ema[MD], g_oc[MD];
__device__ float g_pg[Mrows*Hh];                 // running gamma product within chunk
__device__ float g_sst[Bb*Hh*NCk*DHd];           // chunk start states
__device__ __nv_bfloat16 g_xh[MD], g_xl[MD];
__device__ __nv_bfloat16 g_och[MD], g_ocl[MD];
__device__ __nv_bfloat16 g_wth[4*Dm*Dm], g_wtl[4*Dm*Dm];
__device__ __nv_bfloat16 g_wqh[Bb*Hh*NCk*64*256], g_wql[Bb*Hh*NCk*64*256];
__device__ __nv_bfloat16 g_kth[Bb*Hh*NCk*256*32], g_ktl[Bb*Hh*NCk*256*32];

__device__ __forceinline__ float sigm(float x){ return 1.0f/(1.0f+__expf(-x)); }

__device__ __forceinline__ uint32_t smem_u32(const void* p){
    uint32_t a;
    asm("{ .reg .u64 t; cvta.to.shared.u64 t, %1; cvt.u32.u64 %0, t; }" : "=r"(a) : "l"(p));
    return a;
}
__device__ __forceinline__ uint32_t sw128(uint32_t b){ return b ^ ((b >> 3) & 0x70); }

__device__ __forceinline__ void cpa16(uint32_t dst, const void* src){
    asm volatile("cp.async.cg.shared.global [%0], [%1], 16;" :: "r"(dst), "l"(src) : "memory");
}
#define CP_COMMIT() asm volatile("cp.async.commit_group;" ::: "memory")
#define CP_WAIT(n)  asm volatile("cp.async.wait_group %0;" :: "n"(n) : "memory")

#define LDSM_X4(r0,r1,r2,r3, addr) \
    asm volatile("ldmatrix.sync.aligned.m8n8.x4.shared.b16 {%0,%1,%2,%3}, [%4];" \
        : "=r"(r0),"=r"(r1),"=r"(r2),"=r"(r3) : "r"(addr))
#define LDSM_X4T(r0,r1,r2,r3, addr) \
    asm volatile("ldmatrix.sync.aligned.m8n8.x4.trans.shared.b16 {%0,%1,%2,%3}, [%4];" \
        : "=r"(r0),"=r"(r1),"=r"(r2),"=r"(r3) : "r"(addr))

#define MMA16816(d, a, b) \
    asm volatile("mma.sync.aligned.m16n8k16.row.col.f32.bf16.bf16.f32 " \
        "{%0,%1,%2,%3}, {%4,%5,%6,%7}, {%8,%9}, {%0,%1,%2,%3};" \
        : "+f"((d)[0]),"+f"((d)[1]),"+f"((d)[2]),"+f"((d)[3]) \
        : "r"((a)[0]),"r"((a)[1]),"r"((a)[2]),"r"((a)[3]), "r"((b)[0]),"r"((b)[1]))

__device__ __forceinline__ void split2(float a, float b, uint32_t &hi, uint32_t &lo){
    __nv_bfloat16 ah = __float2bfloat16(a), bh = __float2bfloat16(b);
    __nv_bfloat16 al = __float2bfloat16(a - __bfloat162float(ah));
    __nv_bfloat16 bl = __float2bfloat16(b - __bfloat162float(bh));
    hi = ((uint32_t)__bfloat16_as_ushort(bh) << 16) | (uint32_t)__bfloat16_as_ushort(ah);
    lo = ((uint32_t)__bfloat16_as_ushort(bl) << 16) | (uint32_t)__bfloat16_as_ushort(al);
}

// ================= HMMA GEMM: 128x64 tile, BK=64, 2 stages, 2 CTA/SM, z-fused ===
#define TILEA2 16384
#define TILEB2 8192
#define STAGE2 (2*TILEA2 + 2*TILEB2)   // 49152

__global__ __launch_bounds__(256,2) void mma_gemm_kernel(
    const __nv_bfloat16* __restrict__ Ah, const __nv_bfloat16* __restrict__ Al,
    const __nv_bfloat16* __restrict__ BtHbase, const __nv_bfloat16* __restrict__ BtLbase,
    int woff, float* __restrict__ C0, float* __restrict__ C1, float* __restrict__ C2)
{
    extern __shared__ char dyn[];
    uint32_t raw = smem_u32(dyn);
    uint32_t base = (raw + 127u) & ~127u;

    int z = blockIdx.z;
    const __nv_bfloat16* Bth = BtHbase + (size_t)(woff + z) * Dm * Dm;
    const __nv_bfloat16* Btl = BtLbase + (size_t)(woff + z) * Dm * Dm;
    float* C = (z == 0) ? C0 : ((z == 1) ? C1 : C2);

    int tid = threadIdx.x, lane = tid & 31, wid = tid >> 5;
    int wm = wid >> 1, wn = wid & 1;
    int m0 = blockIdx.y * 128, n0 = blockIdx.x * 64;

    const __nv_bfloat16* gAh = Ah  + (size_t)m0 * Dm;
    const __nv_bfloat16* gAl = Al  + (size_t)m0 * Dm;
    const __nv_bfloat16* gBh = Bth + (size_t)n0 * Dm;
    const __nv_bfloat16* gBl = Btl + (size_t)n0 * Dm;

    float acc[2][4][4];
#pragma unroll
    for (int f=0; f<2; f++)
#pragma unroll
        for (int j=0; j<4; j++)
#pragma unroll
            for (int e=0; e<4; e++) acc[f][j][e] = 0.0f;

    {
        uint32_t sb = base;
#pragma unroll
        for (int t=0;t<4;t++){
            int c = tid + t*256;
            int row = c >> 3, col = c & 7;
            size_t go = (size_t)row*Dm + col*8;
            uint32_t so = sw128((uint32_t)(row*128 + col*16));
            cpa16(sb + so,          gAh + go);
            cpa16(sb + TILEA2 + so, gAl + go);
        }
#pragma unroll
        for (int t=0;t<2;t++){
            int c = tid + t*256;
            int row = c >> 3, col = c & 7;
            size_t go = (size_t)row*Dm + col*8;
            uint32_t so = sw128((uint32_t)(row*128 + col*16));
            cpa16(sb + 2*TILEA2 + so,          gBh + go);
            cpa16(sb + 2*TILEA2 + TILEB2 + so, gBl + go);
        }
        CP_COMMIT();
    }

    const int NSTEP = Dm / 64;
    for (int s = 0; s < NSTEP; s++){
        if (s < NSTEP-1){
            uint32_t sb = base + ((s+1)&1)*STAGE2;
            int k0 = (s+1)*64;
#pragma unroll
            for (int t=0;t<4;t++){
                int c = tid + t*256;
                int row = c >> 3, col = c & 7;
                size_t go = (size_t)row*Dm + k0 + col*8;
                uint32_t so = sw128((uint32_t)(row*128 + col*16));
                cpa16(sb + so,          gAh + go);
                cpa16(sb + TILEA2 + so, gAl + go);
            }
#pragma unroll
            for (int t=0;t<2;t++){
                int c = tid + t*256;
                int row = c >> 3, col = c & 7;
                size_t go = (size_t)row*Dm + k0 + col*8;
                uint32_t so = sw128((uint32_t)(row*128 + col*16));
                cpa16(sb + 2*TILEA2 + so,          gBh + go);
                cpa16(sb + 2*TILEA2 + TILEB2 + so, gBl + go);
            }
            CP_COMMIT();
            CP_WAIT(1);
        } else {
            CP_WAIT(0);
        }
        __syncthreads();

        uint32_t sb = base + (s&1)*STAGE2;
#pragma unroll
        for (int kk = 0; kk < 4; kk++){
            uint32_t ah[2][4], al[2][4];
#pragma unroll
            for (int f=0; f<2; f++){
                int arow = wm*32 + f*16 + (lane & 7) + ((lane >> 3) & 1)*8;
                uint32_t ab = sw128((uint32_t)(arow*128 + kk*32 + (lane >> 4)*16));
                LDSM_X4(ah[f][0],ah[f][1],ah[f][2],ah[f][3], sb + ab);
                LDSM_X4(al[f][0],al[f][1],al[f][2],al[f][3], sb + TILEA2 + ab);
            }
            uint32_t bfrag[4][2];
#pragma unroll
            for (int g=0; g<2; g++){
                int nrow = wn*32 + g*16 + (lane & 7) + ((lane >> 4) << 3);
                uint32_t bb = sw128((uint32_t)(nrow*128 + kk*32 + ((lane >> 3) & 1)*16));
                uint32_t r0,r1,r2,r3;
                LDSM_X4(r0,r1,r2,r3, sb + 2*TILEA2 + bb);
                bfrag[2*g][0]=r0; bfrag[2*g][1]=r1; bfrag[2*g+1][0]=r2; bfrag[2*g+1][1]=r3;
            }
#pragma unroll
            for (int f=0; f<2; f++)
#pragma unroll
                for (int j=0; j<4; j++){
                    MMA16816(acc[f][j], ah[f], bfrag[j]);
                    MMA16816(acc[f][j], al[f], bfrag[j]);
                }
#pragma unroll
            for (int g=0; g<2; g++){
                int nrow = wn*32 + g*16 + (lane & 7) + ((lane >> 4) << 3);
                uint32_t bb = sw128((uint32_t)(nrow*128 + kk*32 + ((lane >> 3) & 1)*16));
                uint32_t r0,r1,r2,r3;
                LDSM_X4(r0,r1,r2,r3, sb + 2*TILEA2 + TILEB2 + bb);
                bfrag[2*g][0]=r0; bfrag[2*g][1]=r1; bfrag[2*g+1][0]=r2; bfrag[2*g+1][1]=r3;
            }
#pragma unroll
            for (int f=0; f<2; f++)
#pragma unroll
                for (int j=0; j<4; j++)
                    MMA16816(acc[f][j], ah[f], bfrag[j]);
        }
        __syncthreads();
    }

#pragma unroll
    for (int f=0; f<2; f++){
        int r = m0 + wm*32 + f*16 + (lane >> 2);
#pragma unroll
        for (int j=0; j<4; j++){
            int cc = n0 + wn*32 + j*8 + (lane & 3)*2;
            *(float2*)&C[(size_t)r*Dm + cc]     = make_float2(acc[f][j][0], acc[f][j][1]);
            *(float2*)&C[(size_t)(r+8)*Dm + cc] = make_float2(acc[f][j][2], acc[f][j][3]);
        }
    }
}

// ================= hi/lo split =================
__global__ void split_bf16_kernel(const float* __restrict__ src,
                                  __nv_bfloat16* __restrict__ hi,
                                  __nv_bfloat16* __restrict__ lo, int n)
{
    int i = blockIdx.x * blockDim.x + threadIdx.x;
    if (i < n){
        float x = src[i];
        __nv_bfloat16 h = __float2bfloat16(x);
        hi[i] = h;
        lo[i] = __float2bfloat16(x - __bfloat162float(h));
    }
}

__global__ void wsplit_kernel(const float* __restrict__ W,
                              __nv_bfloat16* __restrict__ th,
                              __nv_bfloat16* __restrict__ tl)
{
    __shared__ float tile[32][33];
    int n0 = blockIdx.x * 32, k0 = blockIdx.y * 32;
    int tx = threadIdx.x, ty = threadIdx.y;
    for (int r = ty; r < 32; r += 8) tile[r][tx] = W[(size_t)(k0 + r) * Dm + n0 + tx];
    __syncthreads();
    for (int r = ty; r < 32; r += 8){
        float x = tile[tx][r];
        __nv_bfloat16 h = __float2bfloat16(x);
        th[(size_t)(n0 + r) * Dm + k0 + tx] = h;
        tl[(size_t)(n0 + r) * Dm + k0 + tx] = __float2bfloat16(x - __bfloat162float(h));
    }
}

// ---------------- small projections ----------------
__global__ __launch_bounds__(256) void proj_small_kernel(const float* __restrict__ X,
                                                         const float* __restrict__ Wb_,
                                                         const float* __restrict__ Wd_,
                                                         const float* __restrict__ Wm_)
{
    __shared__ float4 wb[256], wd[256], wm[256];
    int tid = threadIdx.x, lane = tid & 31, wid = tid >> 5;
    int t = blockIdx.x * 8 + wid;
    float acc[12];
#pragma unroll
    for (int i=0;i<12;i++) acc[i]=0.0f;
    for (int e0 = 0; e0 < 1024; e0 += 256){
        __syncthreads();
        wb[tid] = ((const float4*)Wb_)[e0 + tid];
        wd[tid] = ((const float4*)Wd_)[e0 + tid];
        wm[tid] = ((const float4*)Wm_)[e0 + tid];
        __syncthreads();
        for (int e = lane; e < 256; e += 32){
            float xv = X[(size_t)t*Dm + e0 + e];
            float4 b = wb[e], d = wd[e], m = wm[e];
            acc[0]+=xv*b.x; acc[1]+=xv*b.y; acc[2]+=xv*b.z; acc[3]+=xv*b.w;
            acc[4]+=xv*d.x; acc[5]+=xv*d.y; acc[6]+=xv*d.z; acc[7]+=xv*d.w;
            acc[8]+=xv*m.x; acc[9]+=xv*m.y; acc[10]+=xv*m.z; acc[11]+=xv*m.w;
        }
    }
#pragma unroll
    for (int i=0;i<12;i++){
        float s = acc[i];
        for (int o=16;o;o>>=1) s += __shfl_xor_sync(0xffffffffu, s, o);
        acc[i] = s;
    }
    if (lane == 0){
#pragma unroll
        for (int c=0;c<4;c++){
            g_beta [t*Hh+c] = sigm(acc[c]);
            g_gamma[t*Hh+c] = sigm(acc[4+c]);
            g_mixlin[t*Hh+c] = acc[8+c];
        }
    }
}

// ---------------- fused depthwise causal conv + silu (q,k,v) --------
__global__ void conv_silu3_kernel(const float* __restrict__ l0, const float* __restrict__ l1,
                                  const float* __restrict__ l2,
                                  const float* __restrict__ c0, const float* __restrict__ c1,
                                  const float* __restrict__ c2,
                                  float* __restrict__ o0, float* __restrict__ o1,
                                  float* __restrict__ o2)
{
    int which = blockIdx.y;
    const float* lin = (which==0)?l0:((which==1)?l1:l2);
    const float* cw  = (which==0)?c0:((which==1)?c1:c2);
    float* out       = (which==0)?o0:((which==1)?o1:o2);
    int dsilu = (which < 2);
    int e = blockIdx.x*blockDim.x + threadIdx.x;
    int t = e / Dm, c = e % Dm;
    int tl = t % Lseq;
    float w0=cw[c*4+0], w1=cw[c*4+1], w2=cw[c*4+2], w3=cw[c*4+3];
    float acc = lin[e]*w3;
    if (tl>=1) acc += lin[e-Dm]*w2;
    if (tl>=2) acc += lin[e-2*Dm]*w1;
    if (tl>=3) acc += lin[e-3*Dm]*w0;
    float y = acc * sigm(acc);
    if (dsilu) y = y * sigm(y);
    out[e] = y;
}

__global__ void conv_mix_kernel(const float* __restrict__ cm, const float* __restrict__ mbias)
{
    int e = blockIdx.x*blockDim.x + threadIdx.x;
    if (e >= Mrows*Hh) return;
    int t = e / Hh, h = e % Hh;
    int tl = t % Lseq;
    float w0=cm[h*4+0], w1=cm[h*4+1], w2=cm[h*4+2], w3=cm[h*4+3];
    float acc = g_mixlin[e]*w3;
    if (tl>=1) acc += g_mixlin[e-Hh]*w2;
    if (tl>=2) acc += g_mixlin[e-2*Hh]*w1;
    if (tl>=3) acc += g_mixlin[e-3*Hh]*w0;
    float y = acc * sigm(acc);
    g_mix[e] = sigm(y + mbias[h]);
}

// ---------------- per-chunk precompute (register-tiled) ----------------
#define SQS 260
__global__ __launch_bounds__(256) void chunk_pre_kernel()
{
    extern __shared__ float sm4[];
    float* sq  = sm4;               // 32*260
    float* skk = sq  + 32*SQS;
    float* sv  = skk + 32*SQS;
    float* sT  = sv  + 32*SQS;      // 1024
    float* sb  = sT  + 1024;        // 32
    int z = blockIdx.x;
    int b  = z >> 8;
    int h  = (z >> 6) & 3;
    int nc = z & 63;
    int t0 = b*Lseq + nc*CHK;
    int cb = h*DHd;
    int tid = threadIdx.x, lane = tid & 31, wid = tid >> 5;

    for (int e=tid; e<32*64; e+=256){
        int r=e>>6, c=(e&63)*4;
        *(float4*)&sq [r*SQS+c] = *(const float4*)&g_q[(size_t)(t0+r)*Dm + cb + c];
        *(float4*)&skk[r*SQS+c] = *(const float4*)&g_k[(size_t)(t0+r)*Dm + cb + c];
        *(float4*)&sv [r*SQS+c] = *(const float4*)&g_v[(size_t)(t0+r)*Dm + cb + c];
    }
    if (tid < 32) sb[tid] = g_beta[(t0+tid)*Hh + h];
    __syncthreads();

    // row l2norm for q and k
    for (int r=wid; r<32; r+=8){
        float s=0.0f;
        for (int c=lane;c<256;c+=32){ float v=sq[r*SQS+c]; s+=v*v; }
        for (int o=16;o;o>>=1) s += __shfl_xor_sync(0xffffffffu,s,o);
        float rn = rsqrtf(s + 1e-6f);
        for (int c=lane;c<256;c+=32){ sq[r*SQS+c] *= rn; }
        s=0.0f;
        for (int c=lane;c<256;c+=32){ float v=skk[r*SQS+c]; s+=v*v; }
        for (int o=16;o;o>>=1) s += __shfl_xor_sync(0xffffffffu,s,o);
        rn = rsqrtf(s + 1e-6f);
        for (int c=lane;c<256;c+=32){ skk[r*SQS+c] *= rn; }
    }
    __syncthreads();

    // tiled dot products: attn = K·K^T (for sT) and A2 = Q·K^T
    {
        int ti = tid >> 4, tj = tid & 15;
        int i0 = 2*ti, j0 = 2*tj;
        float a00=0,a01=0,a10=0,a11=0;
        float q00=0,q01=0,q10=0,q11=0;
#pragma unroll 8
        for (int p=0;p<256;p+=4){
            float4 ki0 = *(float4*)&skk[i0*SQS+p];
            float4 ki1 = *(float4*)&skk[(i0+1)*SQS+p];
            float4 qi0 = *(float4*)&sq [i0*SQS+p];
            float4 qi1 = *(float4*)&sq [(i0+1)*SQS+p];
            float4 kj0 = *(float4*)&skk[j0*SQS+p];
            float4 kj1 = *(float4*)&skk[(j0+1)*SQS+p];
            a00 += ki0.x*kj0.x + ki0.y*kj0.y + ki0.z*kj0.z + ki0.w*kj0.w;
            a01 += ki0.x*kj1.x + ki0.y*kj1.y + ki0.z*kj1.z + ki0.w*kj1.w;
            a10 += ki1.x*kj0.x + ki1.y*kj0.y + ki1.z*kj0.z + ki1.w*kj0.w;
            a11 += ki1.x*kj1.x + ki1.y*kj1.y + ki1.z*kj1.z + ki1.w*kj1.w;
            q00 += qi0.x*kj0.x + qi0.y*kj0.y + qi0.z*kj0.z + qi0.w*kj0.w;
            q01 += qi0.x*kj1.x + qi0.y*kj1.y + qi0.z*kj1.z + qi0.w*kj1.w;
            q10 += qi1.x*kj0.x + qi1.y*kj0.y + qi1.z*kj0.z + qi1.w*kj0.w;
            q11 += qi1.x*kj1.x + qi1.y*kj1.y + qi1.z*kj1.z + qi1.w*kj1.w;
        }
        sT[i0*32+j0]       = (j0   < i0  ) ? -sb[i0]*a00   : 0.0f;
        sT[i0*32+j0+1]     = (j0+1 < i0  ) ? -sb[i0]*a01   : 0.0f;
        sT[(i0+1)*32+j0]   = (j0   < i0+1) ? -sb[i0+1]*a10 : 0.0f;
        sT[(i0+1)*32+j0+1] = (j0+1 < i0+1) ? -sb[i0+1]*a11 : 0.0f;
        size_t abase = (size_t)z*1024;
        g_A2[abase + i0*32+j0]       = (j0   <= i0  ) ? q00 : 0.0f;
        g_A2[abase + i0*32+j0+1]     = (j0+1 <= i0  ) ? q01 : 0.0f;
        g_A2[abase + (i0+1)*32+j0]   = (j0   <= i0+1) ? q10 : 0.0f;
        g_A2[abase + (i0+1)*32+j0+1] = (j0+1 <= i0+1) ? q11 : 0.0f;
    }
    __syncthreads();

    // forward substitution (warp 0), then +I
    if (wid == 0){
        for (int i=1;i<32;i++){
            float a = sT[i*32+lane];
            float acc = 0.0f;
            for (int j=1;j<32;j++){
                float aij = __shfl_sync(0xffffffffu, a, j);
                acc += aij * sT[j*32+lane];
            }
            if (lane < i) sT[i*32+lane] = a + acc;
            __syncwarp();
        }
        sT[lane*32+lane] += 1.0f;
    }
    __syncthreads();

    // scale: Tb[i][j] = T[i][j]*beta[j]
    for (int e=tid; e<1024; e+=256) sT[e] *= sb[e&31];
    __syncthreads();

    // u = Tb@v, w = Tb@k  -> tiled 8 rows x 4 cols per thread
    size_t wqb = (size_t)z*16384;
    {
        int ri = tid >> 6;          // 0..3 -> rows ri*8..+7
        int tc = (tid & 63) * 4;    // col group
        float4 ua[8], wa[8];
#pragma unroll
        for (int r=0;r<8;r++){ ua[r]=make_float4(0,0,0,0); wa[r]=make_float4(0,0,0,0); }
        for (int j=0;j<32;j++){
            float4 v4 = *(float4*)&sv [j*SQS + tc];
            float4 k4 = *(float4*)&skk[j*SQS + tc];
#pragma unroll
            for (int r=0;r<8;r++){
                float tb = sT[(ri*8+r)*32 + j];
                ua[r].x += tb*v4.x; ua[r].y += tb*v4.y; ua[r].z += tb*v4.z; ua[r].w += tb*v4.w;
                wa[r].x += tb*k4.x; wa[r].y += tb*k4.y; wa[r].z += tb*k4.z; wa[r].w += tb*k4.w;
            }
        }
#pragma unroll
        for (int r=0;r<8;r++){
            int i = ri*8 + r;
            *(float4*)&g_u[(size_t)(t0+i)*Dm + cb + tc] = ua[r];
            uint32_t hw0, lw0, hw1, lw1;
            split2(wa[r].x, wa[r].y, hw0, lw0);
            split2(wa[r].z, wa[r].w, hw1, lw1);
            *(uint2*)&g_wqh[wqb + i*256 + tc] = make_uint2(hw0, hw1);
            *(uint2*)&g_wql[wqb + i*256 + tc] = make_uint2(lw0, lw1);
            // q rows 32..63
            float4 q4 = *(float4*)&sq[i*SQS + tc];
            split2(q4.x, q4.y, hw0, lw0);
            split2(q4.z, q4.w, hw1, lw1);
            *(uint2*)&g_wqh[wqb + (32+i)*256 + tc] = make_uint2(hw0, hw1);
            *(uint2*)&g_wql[wqb + (32+i)*256 + tc] = make_uint2(lw0, lw1);
        }
    }

    // k^T hi/lo [256][32]
    size_t ktb = (size_t)z*8192;
    for (int e=tid; e<8192; e+=256){
        int r=e>>5, j=e&31;
        float kv = skk[j*SQS + r];
        __nv_bfloat16 kh = __float2bfloat16(kv);
        g_kth[ktb + r*32 + j] = kh;
        g_ktl[ktb + r*32 + j] = __float2bfloat16(kv - __bfloat162float(kh));
    }
}

// ---------------- MMA recurrence, dv-sliced ----------------
__global__ __launch_bounds__(256) void recurrence_kernel()
{
    extern __shared__ char sm5[];
    uint32_t raw = smem_u32(sm5);
    uint32_t base = (raw + 127u) & ~127u;
    char* p0 = sm5 + (base - raw);

    const uint32_t oWQh = 0, oWQl = 32768, oSh = 65536, oSl = 86016;
    const uint32_t oKTh = 106496, oKTl = 126976, oUAh = 147456, oUAl = 150016;
    const uint32_t oU = 152576, oA2 = 157184, oRq = 161792, oUA32 = 166400;

    uint32_t uWQh = base+oWQh, uWQl = base+oWQl, uSh = base+oSh, uSl = base+oSl;
    uint32_t uKTh = base+oKTh, uKTl = base+oKTl, uUAh = base+oUAh, uUAl = base+oUAl;
    float* u_s  = (float*)(p0 + oU);
    float* A2_s = (float*)(p0 + oA2);
    float* Rq_s = (float*)(p0 + oRq);
    float* ua_s = (float*)(p0 + oUA32);
    char* pSh = p0 + oSh; char* pSl = p0 + oSl;
    char* pUAh = p0 + oUAh; char* pUAl = p0 + oUAl;

    int bx = blockIdx.x;
    int bh = bx >> 3, vb = bx & 7;
    int b = bh >> 2, h = bx >> 3 & 3;
    int cvb = h*DHd + vb*32;
    int tid = threadIdx.x, lane = tid & 31, wid = tid >> 5;
    int rm = wid >> 1, rn = wid & 1;

    float accS[2][4][4];
#pragma unroll
    for (int tm=0;tm<2;tm++)
#pragma unroll
        for (int tn=0;tn<4;tn++)
#pragma unroll
            for (int e=0;e<4;e++) accS[tm][tn][e]=0.0f;

    for (int ci=0; ci<NCk; ci++){
        __syncthreads();
        int slot = bh*NCk + ci;
        int t0 = b*Lseq + ci*CHK;
        const __nv_bfloat16* gwqh = g_wqh + (size_t)slot*16384;
        const __nv_bfloat16* gwql = g_wql + (size_t)slot*16384;
        const __nv_bfloat16* gkth = g_kth + (size_t)slot*8192;
        const __nv_bfloat16* gktl = g_ktl + (size_t)slot*8192;

#pragma unroll
        for (int t=0;t<8;t++){
            int c = tid + t*256;
            int row = c >> 5, col = c & 31;
            uint32_t dst = row*512 + ((uint32_t)(col ^ (row & 7)) << 4);
            cpa16(uWQh + dst, gwqh + c*8);
            cpa16(uWQl + dst, gwql + c*8);
        }
#pragma unroll
        for (int t=0;t<4;t++){
            int c = tid + t*256;
            int row = c >> 2, col = c & 3;
            uint32_t dst = row*80 + (col << 4);
            cpa16(uKTh + dst, gkth + c*8);
            cpa16(uKTl + dst, gktl + c*8);
        }
        {
            int row = tid >> 3, col = tid & 7;
            cpa16(base + oU + row*144 + col*16, &g_u[(size_t)(t0+row)*Dm + cvb + col*4]);
            cpa16(base + oA2 + row*144 + col*16, g_A2 + (size_t)slot*1024 + tid*4);
        }
        CP_COMMIT();

#pragma unroll
        for (int tm=0;tm<2;tm++)
#pragma unroll
        for (int tn=0;tn<4;tn++){
            int r = wid*32 + tm*16 + (lane>>2);
            int c = tn*8 + (lane&3)*2;
            uint32_t hw, lw;
            split2(accS[tm][tn][0], accS[tm][tn][1], hw, lw);
            *(uint32_t*)(pSh + r*80 + c*2) = hw;
            *(uint32_t*)(pSl + r*80 + c*2) = lw;
            split2(accS[tm][tn][2], accS[tm][tn][3], hw, lw);
            *(uint32_t*)(pSh + (r+8)*80 + c*2) = hw;
            *(uint32_t*)(pSl + (r+8)*80 + c*2) = lw;
        }

        CP_WAIT(0);
        __syncthreads();

        float accR[2][4];
#pragma unroll
        for (int j=0;j<2;j++)
#pragma unroll
            for (int e=0;e<4;e++) accR[j][e]=0.0f;

#pragma unroll 4
        for (int kk=0; kk<16; kk++){
            int arow = rm*16 + (lane & 7) + ((lane >> 3) & 1)*8;
            int achunk = kk*2 + (lane >> 4);
            uint32_t aoff = arow*512 + ((uint32_t)(achunk ^ (arow & 7)) << 4);
            uint32_t ah[4], al[4];
            LDSM_X4(ah[0],ah[1],ah[2],ah[3], uWQh + aoff);
            LDSM_X4(al[0],al[1],al[2],al[3], uWQl + aoff);

            int krow = kk*16 + (lane & 7) + ((lane >> 3) & 1)*8;
            uint32_t boff = krow*80 + rn*32 + ((lane >> 4) << 4);
            uint32_t s0,s1,s2,s3;
            LDSM_X4T(s0,s1,s2,s3, uSh + boff);
            uint32_t bh0[2] = {s0,s1}, bh1[2] = {s2,s3};
            LDSM_X4T(s0,s1,s2,s3, uSl + boff);
            uint32_t bl0[2] = {s0,s1}, bl1[2] = {s2,s3};

            MMA16816(accR[0], ah, bh0);
            MMA16816(accR[0], al, bh0);
            MMA16816(accR[0], ah, bl0);
            MMA16816(accR[1], ah, bh1);
            MMA16816(accR[1], al, bh1);
            MMA16816(accR[1], ah, bl1);
        }

        if (wid < 4){
#pragma unroll
            for (int j=0;j<2;j++){
                int c = rn*16 + j*8 + (lane&3)*2;
                int r1 = rm*16 + (lane>>2);
                float ua0 = u_s[r1*36+c]   - accR[j][0];
                float ua1 = u_s[r1*36+c+1] - accR[j][1];
                uint32_t hw, lw;
                split2(ua0, ua1, hw, lw);
                *(uint32_t*)(pUAh + r1*80 + c*2) = hw;
                *(uint32_t*)(pUAl + r1*80 + c*2) = lw;
                *(float2*)&ua_s[r1*36+c] = make_float2(ua0, ua1);
                float ua2 = u_s[(r1+8)*36+c]   - accR[j][2];
                float ua3 = u_s[(r1+8)*36+c+1] - accR[j][3];
                split2(ua2, ua3, hw, lw);
                *(uint32_t*)(pUAh + (r1+8)*80 + c*2) = hw;
                *(uint32_t*)(pUAl + (r1+8)*80 + c*2) = lw;
                *(float2*)&ua_s[(r1+8)*36+c] = make_float2(ua2, ua3);
            }
        } else {
#pragma unroll
            for (int j=0;j<2;j++){
                int c = rn*16 + j*8 + (lane&3)*2;
                int r1 = (rm-2)*16 + (lane>>2);
                *(float2*)&Rq_s[r1*36+c]     = make_float2(accR[j][0], accR[j][1]);
                *(float2*)&Rq_s[(r1+8)*36+c] = make_float2(accR[j][2], accR[j][3]);
            }
        }
        __syncthreads();

        {
            int c = tid & 31, rb = tid >> 5;
            float o0 = Rq_s[rb*36+c], o1 = Rq_s[(rb+8)*36+c];
            float o2 = Rq_s[(rb+16)*36+c], o3 = Rq_s[(rb+24)*36+c];
#pragma unroll 8
            for (int j=0;j<32;j++){
                float uv = ua_s[j*36+c];
                o0 += A2_s[rb*36+j]*uv;
                o1 += A2_s[(rb+8)*36+j]*uv;
                o2 += A2_s[(rb+16)*36+j]*uv;
                o3 += A2_s[(rb+24)*36+j]*uv;
            }
            g_od[(size_t)(t0+rb)*Dm + cvb + c]      = o0;
            g_od[(size_t)(t0+rb+8)*Dm + cvb + c]    = o1;
            g_od[(size_t)(t0+rb+16)*Dm + cvb + c]   = o2;
            g_od[(size_t)(t0+rb+24)*Dm + cvb + c]   = o3;
        }

#pragma unroll
        for (int kk=0; kk<2; kk++){
            uint32_t a_h[2][4], a_l[2][4];
#pragma unroll
            for (int tm=0;tm<2;tm++){
                int mrow = wid*32 + tm*16 + (lane & 7) + ((lane >> 3) & 1)*8;
                uint32_t aoff = mrow*80 + kk*32 + ((lane >> 4) << 4);
                LDSM_X4(a_h[tm][0],a_h[tm][1],a_h[tm][2],a_h[tm][3], uKTh + aoff);
                LDSM_X4(a_l[tm][0],a_l[tm][1],a_l[tm][2],a_l[tm][3], uKTl + aoff);
            }
            uint32_t bu_h[4][2], bu_l[4][2];
#pragma unroll
            for (int g=0; g<2; g++){
                int krow = kk*16 + (lane & 7) + ((lane >> 3) & 1)*8;
                uint32_t boff = krow*80 + g*32 + ((lane >> 4) << 4);
                uint32_t r0,r1,r2,r3;
                LDSM_X4T(r0,r1,r2,r3, uUAh + boff);
                bu_h[2*g][0]=r0; bu_h[2*g][1]=r1; bu_h[2*g+1][0]=r2; bu_h[2*g+1][1]=r3;
                LDSM_X4T(r0,r1,r2,r3, uUAl + boff);
                bu_l[2*g][0]=r0; bu_l[2*g][1]=r1; bu_l[2*g+1][0]=r2; bu_l[2*g+1][1]=r3;
            }
#pragma unroll
            for (int tm=0;tm<2;tm++)
#pragma unroll
                for (int tn=0;tn<4;tn++){
                    MMA16816(accS[tm][tn], a_h[tm], bu_h[tn]);
                    MMA16816(accS[tm][tn], a_l[tm], bu_h[tn]);
                    MMA16816(accS[tm][tn], a_h[tm], bu_l[tn]);
                }
        }
    }
}

// ---------------- EMA chunked scan ----------------
// Pass A: chunk-local scan + gamma prefix products. grid = Bb*Hh*NCk
__global__ void ema_chunk_kernel()
{
    int z = blockIdx.x;
    int b = z >> 8, h = (z >> 6) & 3, nc = z & 63;
    int t0 = b*Lseq + nc*CHK;
    int cb = h*DHd;
    int c = threadIdx.x;
    float s = 0.0f, pg = 1.0f;
    for (int t=0;t<CHK;t++){
        int row = t0 + t;
        float g = g_gamma[row*Hh + h];
        float v = g_v[(size_t)row*Dm + cb + c];
        s = g*s + (1.0f-g)*v;
        pg *= g;
        g_ema[(size_t)row*Dm + cb + c] = s;
        if (c == 0) g_pg[row*Hh + h] = pg;
    }
}

// Pass B: cross-chunk scan. grid = Bb*Hh
__global__ void ema_seq_kernel()
{
    int bh = blockIdx.x;
    int b = bh >> 2, h = bh & 3;
    int cb = h*DHd;
    int c = threadIdx.x;
    float S = 0.0f;
    for (int j=0;j<NCk;j++){
        g_sst[(size_t)(bh*NCk + j)*DHd + c] = S;
        int rowE = b*Lseq + j*CHK + CHK-1;
        float E = g_ema[(size_t)rowE*Dm + cb + c];
        float P = g_pg[rowE*Hh + h];
        S = E + P*S;
    }
}

// ---------------- mix + rmsnorm (applies EMA correction) ----------------
__global__ __launch_bounds__(256) void combine_kernel(const float* __restrict__ rmsw)
{
    int t = blockIdx.x, c = threadIdx.x;
    int b = t / Lseq, tl = t % Lseq, chunk = tl >> 5;
    __shared__ float red[8];
    for (int h=0;h<Hh;h++){
        float mix = g_mix[t*Hh+h];
        size_t idx = (size_t)t*Dm + h*DHd + c;
        float ema = g_ema[idx] + g_pg[t*Hh+h] * g_sst[(size_t)((b*4+h)*NCk + chunk)*DHd + c];
        float o = (1.0f-mix)*g_od[idx] + mix*ema;
        float s = o*o;
        for (int off=16;off;off>>=1) s += __shfl_xor_sync(0xffffffffu,s,off);
        if ((c&31)==0) red[c>>5]=s;
        __syncthreads();
        float tot = red[0]+red[1]+red[2]+red[3]+red[4]+red[5]+red[6]+red[7];
        float scale = rsqrtf(tot*(1.0f/256.0f) + 1e-5f);
        g_oc[idx] = o*scale*rmsw[c];
        __syncthreads();
    }
}

// ---------------- launcher ----------------
extern "C" void kernel_launch(void* const* d_in, const int* in_sizes, int n_in,
                              void* d_out, int out_size)
{
    const float* X    = (const float*)d_in[0];
    const float* Wq   = (const float*)d_in[1];
    const float* Wk   = (const float*)d_in[2];
    const float* Wv   = (const float*)d_in[3];
    const float* cq   = (const float*)d_in[4];
    const float* ck   = (const float*)d_in[5];
    const float* cv   = (const float*)d_in[6];
    const float* Wb   = (const float*)d_in[7];
    const float* Wdec = (const float*)d_in[8];
    const float* Wmix = (const float*)d_in[9];
    const float* cmix = (const float*)d_in[10];
    const float* mbias= (const float*)d_in[11];
    const float* rmsw = (const float*)d_in[12];
    const float* Wo   = (const float*)d_in[13];
    float* out = (float*)d_out;
    (void)in_sizes; (void)n_in; (void)out_size;

    float *p_qlin,*p_klin,*p_vlin,*p_oc,*p_q,*p_k,*p_v;
    __nv_bfloat16 *p_xh,*p_xl,*p_och,*p_ocl,*p_wth,*p_wtl;
    cudaGetSymbolAddress((void**)&p_qlin, g_qlin);
    cudaGetSymbolAddress((void**)&p_klin, g_klin);
    cudaGetSymbolAddress((void**)&p_vlin, g_vlin);
    cudaGetSymbolAddress((void**)&p_oc,   g_oc);
    cudaGetSymbolAddress((void**)&p_xh,   g_xh);
    cudaGetSymbolAddress((void**)&p_xl,   g_xl);
    cudaGetSymbolAddress((void**)&p_och,  g_och);
    cudaGetSymbolAddress((void**)&p_ocl,  g_ocl);
    cudaGetSymbolAddress((void**)&p_wth,  g_wth);
    cudaGetSymbolAddress((void**)&p_wtl,  g_wtl);
    cudaGetSymbolAddress((void**)&p_q, g_q);
    cudaGetSymbolAddress((void**)&p_k, g_k);
    cudaGetSymbolAddress((void**)&p_v, g_v);

    const int WM = Dm*Dm;
    const int SMEMG = 2*STAGE2 + 256;

    cudaFuncSetAttribute(mma_gemm_kernel, cudaFuncAttributeMaxDynamicSharedMemorySize, SMEMG);

    split_bf16_kernel<<<(MD+255)/256,256>>>(X, p_xh, p_xl, MD);
    dim3 wg(32,32), wb2(32,8);
    wsplit_kernel<<<wg,wb2>>>(Wq, p_wth + 0*WM, p_wtl + 0*WM);
    wsplit_kernel<<<wg,wb2>>>(Wk, p_wth + 1*WM, p_wtl + 1*WM);
    wsplit_kernel<<<wg,wb2>>>(Wv, p_wth + 2*WM, p_wtl + 2*WM);
    wsplit_kernel<<<wg,wb2>>>(Wo, p_wth + 3*WM, p_wtl + 3*WM);

    dim3 gg3(Dm/64, Mrows/128, 3);   // fused Q,K,V
    mma_gemm_kernel<<<gg3,256,SMEMG>>>(p_xh, p_xl, p_wth, p_wtl, 0, p_qlin, p_klin, p_vlin);

    proj_small_kernel<<<Mrows/8,256>>>(X, Wb, Wdec, Wmix);

    dim3 cg(MD/256, 3);
    conv_silu3_kernel<<<cg,256>>>(p_qlin, p_klin, p_vlin, cq, ck, cv, p_q, p_k, p_v);
    conv_mix_kernel<<<(Mrows*Hh+255)/256,256>>>(cmix, mbias);

    const int SMEM4 = (3*32*SQS + 1024 + 32) * 4;
    cudaFuncSetAttribute(chunk_pre_kernel, cudaFuncAttributeMaxDynamicSharedMemorySize, SMEM4);
    chunk_pre_kernel<<<Bb*Hh*NCk, 256, SMEM4>>>();

    const int SMEM5 = 171008 + 256;
    cudaFuncSetAttribute(recurrence_kernel, cudaFuncAttributeMaxDynamicSharedMemorySize, SMEM5);
    recurrence_kernel<<<Bb*Hh*8, 256, SMEM5>>>();

    ema_chunk_kernel<<<Bb*Hh*NCk, 256>>>();
    ema_seq_kernel<<<Bb*Hh, 256>>>();
    combine_kernel<<<Mrows,256>>>(rmsw);

    split_bf16_kernel<<<(MD+255)/256,256>>>(p_oc, p_och, p_ocl, MD);
    dim3 gg1(Dm/64, Mrows/128, 1);
    mma_gemm_kernel<<<gg1,256,SMEMG>>>(p_och, p_ocl, p_wth, p_wtl, 3, out, out, out);
}

// round 6
// speedup vs baseline: 5.4268x; 1.4942x over previous
#include <cuda_runtime.h>
#include <cuda_fp16.h>
#include <math.h>
#include <stdint.h>

#define Bb   4
#define Lseq 2048
#define Dm   1024
#define Hh   4
#define DHd  256
#define CHK  32
#define NCk  (Lseq/CHK)      // 64
#define Mrows (Bb*Lseq)      // 8192
#define MD (Mrows*Dm)

// ---------------- scratch ----------------
__device__ float g_qlin[MD], g_klin[MD], g_vlin[MD];
__device__ float g_q[MD], g_k[MD], g_v[MD];
__device__ float g_u[MD];
__device__ float g_A2[Bb*Hh*NCk*CHK*CHK];
__device__ float g_beta[Mrows*Hh], g_gamma[Mrows*Hh], g_mixlin[Mrows*Hh], g_mix[Mrows*Hh];
__device__ float g_od[MD], g_ema[MD];
__device__ float g_pg[Mrows*Hh];
__device__ float g_sst[Bb*Hh*NCk*DHd];
__device__ __half g_x16[MD];
__device__ __half g_oc16[MD];
__device__ __half g_wt16[4*Dm*Dm];                  // transposed [N][K] per matrix
__device__ __half g_wq16[Bb*Hh*NCk*64*256];         // [slot][64][256] (w rows 0-31, q rows 32-63)
__device__ __half g_kt16[Bb*Hh*NCk*256*32];         // [slot][256][32] k^T

__device__ __forceinline__ float sigm(float x){ return 1.0f/(1.0f+__expf(-x)); }

__device__ __forceinline__ uint32_t smem_u32(const void* p){
    uint32_t a;
    asm("{ .reg .u64 t; cvta.to.shared.u64 t, %1; cvt.u32.u64 %0, t; }" : "=r"(a) : "l"(p));
    return a;
}
__device__ __forceinline__ uint32_t sw128(uint32_t b){ return b ^ ((b >> 3) & 0x70); }

__device__ __forceinline__ void cpa16(uint32_t dst, const void* src){
    asm volatile("cp.async.cg.shared.global [%0], [%1], 16;" :: "r"(dst), "l"(src) : "memory");
}
#define CP_COMMIT() asm volatile("cp.async.commit_group;" ::: "memory")
#define CP_WAIT(n)  asm volatile("cp.async.wait_group %0;" :: "n"(n) : "memory")

#define LDSM_X4(r0,r1,r2,r3, addr) \
    asm volatile("ldmatrix.sync.aligned.m8n8.x4.shared.b16 {%0,%1,%2,%3}, [%4];" \
        : "=r"(r0),"=r"(r1),"=r"(r2),"=r"(r3) : "r"(addr))
#define LDSM_X4T(r0,r1,r2,r3, addr) \
    asm volatile("ldmatrix.sync.aligned.m8n8.x4.trans.shared.b16 {%0,%1,%2,%3}, [%4];" \
        : "=r"(r0),"=r"(r1),"=r"(r2),"=r"(r3) : "r"(addr))

#define MMAF16(d, a, b) \
    asm volatile("mma.sync.aligned.m16n8k16.row.col.f32.f16.f16.f32 " \
        "{%0,%1,%2,%3}, {%4,%5,%6,%7}, {%8,%9}, {%0,%1,%2,%3};" \
        : "+f"((d)[0]),"+f"((d)[1]),"+f"((d)[2]),"+f"((d)[3]) \
        : "r"((a)[0]),"r"((a)[1]),"r"((a)[2]),"r"((a)[3]), "r"((b)[0]),"r"((b)[1]))

__device__ __forceinline__ uint32_t f2h2(float a, float b){
    __half2 h = __floats2half2_rn(a, b);
    return *(uint32_t*)&h;
}

// ================= fp16 HMMA GEMM: 128x128 tile, BK=64, 2 stages, 2 CTA/SM ======
#define TILE16 16384             // 128x64 fp16 (128B rows)
#define STAGEF (2*TILE16)        // A + B = 32KB

__global__ __launch_bounds__(256,2) void mma_gemm_kernel(
    const __half* __restrict__ A,
    const __half* __restrict__ BtBase,
    int woff, float* __restrict__ C0, float* __restrict__ C1, float* __restrict__ C2)
{
    extern __shared__ char dyn[];
    uint32_t raw = smem_u32(dyn);
    uint32_t base = (raw + 127u) & ~127u;

    int z = blockIdx.z;
    const __half* Bt = BtBase + (size_t)(woff + z) * Dm * Dm;
    float* C = (z == 0) ? C0 : ((z == 1) ? C1 : C2);

    int tid = threadIdx.x, lane = tid & 31, wid = tid >> 5;
    int wm = wid >> 1, wn = wid & 1;
    int m0 = blockIdx.y * 128, n0 = blockIdx.x * 128;

    const __half* gA = A  + (size_t)m0 * Dm;
    const __half* gB = Bt + (size_t)n0 * Dm;

    float acc[2][8][4];
#pragma unroll
    for (int f=0; f<2; f++)
#pragma unroll
        for (int j=0; j<8; j++)
#pragma unroll
            for (int e=0; e<4; e++) acc[f][j][e] = 0.0f;

    {
        uint32_t sb = base;
#pragma unroll
        for (int t=0;t<4;t++){
            int c = tid + t*256;
            int row = c >> 3, col = c & 7;
            size_t go = (size_t)row*Dm + col*8;
            uint32_t so = sw128((uint32_t)(row*128 + col*16));
            cpa16(sb + so,          gA + go);
            cpa16(sb + TILE16 + so, gB + go);
        }
        CP_COMMIT();
    }

    const int NSTEP = Dm / 64;
    for (int s = 0; s < NSTEP; s++){
        if (s < NSTEP-1){
            uint32_t sb = base + ((s+1)&1)*STAGEF;
            int k0 = (s+1)*64;
#pragma unroll
            for (int t=0;t<4;t++){
                int c = tid + t*256;
                int row = c >> 3, col = c & 7;
                size_t go = (size_t)row*Dm + k0 + col*8;
                uint32_t so = sw128((uint32_t)(row*128 + col*16));
                cpa16(sb + so,          gA + go);
                cpa16(sb + TILE16 + so, gB + go);
            }
            CP_COMMIT();
            CP_WAIT(1);
        } else {
            CP_WAIT(0);
        }
        __syncthreads();

        uint32_t sb = base + (s&1)*STAGEF;
#pragma unroll
        for (int kk = 0; kk < 4; kk++){
            uint32_t af[2][4];
#pragma unroll
            for (int f=0; f<2; f++){
                int arow = wm*32 + f*16 + (lane & 7) + ((lane >> 3) & 1)*8;
                uint32_t ab = sw128((uint32_t)(arow*128 + kk*32 + (lane >> 4)*16));
                LDSM_X4(af[f][0],af[f][1],af[f][2],af[f][3], sb + ab);
            }
            uint32_t bfrag[8][2];
#pragma unroll
            for (int g=0; g<4; g++){
                int nrow = wn*64 + g*16 + (lane & 7) + ((lane >> 4) << 3);
                uint32_t bb = sw128((uint32_t)(nrow*128 + kk*32 + ((lane >> 3) & 1)*16));
                uint32_t r0,r1,r2,r3;
                LDSM_X4(r0,r1,r2,r3, sb + TILE16 + bb);
                bfrag[2*g][0]=r0; bfrag[2*g][1]=r1; bfrag[2*g+1][0]=r2; bfrag[2*g+1][1]=r3;
            }
#pragma unroll
            for (int f=0; f<2; f++)
#pragma unroll
                for (int j=0; j<8; j++)
                    MMAF16(acc[f][j], af[f], bfrag[j]);
        }
        __syncthreads();
    }

#pragma unroll
    for (int f=0; f<2; f++){
        int r = m0 + wm*32 + f*16 + (lane >> 2);
#pragma unroll
        for (int j=0; j<8; j++){
            int cc = n0 + wn*64 + j*8 + (lane & 3)*2;
            *(float2*)&C[(size_t)r*Dm + cc]     = make_float2(acc[f][j][0], acc[f][j][1]);
            *(float2*)&C[(size_t)(r+8)*Dm + cc] = make_float2(acc[f][j][2], acc[f][j][3]);
        }
    }
}

// ================= fp16 conversions =================
__global__ void tohalf_kernel(const float* __restrict__ src, __half* __restrict__ dst, int n)
{
    int i = blockIdx.x * blockDim.x + threadIdx.x;
    if (i < n) dst[i] = __float2half(src[i]);
}

// W [K][N] -> Wt [N][K] fp16
__global__ void wsplit_kernel(const float* __restrict__ W, __half* __restrict__ th)
{
    __shared__ float tile[32][33];
    int n0 = blockIdx.x * 32, k0 = blockIdx.y * 32;
    int tx = threadIdx.x, ty = threadIdx.y;
    for (int r = ty; r < 32; r += 8) tile[r][tx] = W[(size_t)(k0 + r) * Dm + n0 + tx];
    __syncthreads();
    for (int r = ty; r < 32; r += 8)
        th[(size_t)(n0 + r) * Dm + k0 + tx] = __float2half(tile[tx][r]);
}

// ---------------- small projections ----------------
__global__ __launch_bounds__(256) void proj_small_kernel(const float* __restrict__ X,
                                                         const float* __restrict__ Wb_,
                                                         const float* __restrict__ Wd_,
                                                         const float* __restrict__ Wm_)
{
    __shared__ float4 wb[256], wd[256], wm[256];
    int tid = threadIdx.x, lane = tid & 31, wid = tid >> 5;
    int t = blockIdx.x * 8 + wid;
    float acc[12];
#pragma unroll
    for (int i=0;i<12;i++) acc[i]=0.0f;
    for (int e0 = 0; e0 < 1024; e0 += 256){
        __syncthreads();
        wb[tid] = ((const float4*)Wb_)[e0 + tid];
        wd[tid] = ((const float4*)Wd_)[e0 + tid];
        wm[tid] = ((const float4*)Wm_)[e0 + tid];
        __syncthreads();
        for (int e = lane; e < 256; e += 32){
            float xv = X[(size_t)t*Dm + e0 + e];
            float4 b = wb[e], d = wd[e], m = wm[e];
            acc[0]+=xv*b.x; acc[1]+=xv*b.y; acc[2]+=xv*b.z; acc[3]+=xv*b.w;
            acc[4]+=xv*d.x; acc[5]+=xv*d.y; acc[6]+=xv*d.z; acc[7]+=xv*d.w;
            acc[8]+=xv*m.x; acc[9]+=xv*m.y; acc[10]+=xv*m.z; acc[11]+=xv*m.w;
        }
    }
#pragma unroll
    for (int i=0;i<12;i++){
        float s = acc[i];
        for (int o=16;o;o>>=1) s += __shfl_xor_sync(0xffffffffu, s, o);
        acc[i] = s;
    }
    if (lane == 0){
#pragma unroll
        for (int c=0;c<4;c++){
            g_beta [t*Hh+c] = sigm(acc[c]);
            g_gamma[t*Hh+c] = sigm(acc[4+c]);
            g_mixlin[t*Hh+c] = acc[8+c];
        }
    }
}

// ---------------- fused depthwise causal conv + silu (q,k,v) --------
__global__ void conv_silu3_kernel(const float* __restrict__ l0, const float* __restrict__ l1,
                                  const float* __restrict__ l2,
                                  const float* __restrict__ c0, const float* __restrict__ c1,
                                  const float* __restrict__ c2,
                                  float* __restrict__ o0, float* __restrict__ o1,
                                  float* __restrict__ o2)
{
    int which = blockIdx.y;
    const float* lin = (which==0)?l0:((which==1)?l1:l2);
    const float* cw  = (which==0)?c0:((which==1)?c1:c2);
    float* out       = (which==0)?o0:((which==1)?o1:o2);
    int dsilu = (which < 2);
    int e = blockIdx.x*blockDim.x + threadIdx.x;
    int t = e / Dm, c = e % Dm;
    int tl = t % Lseq;
    float w0=cw[c*4+0], w1=cw[c*4+1], w2=cw[c*4+2], w3=cw[c*4+3];
    float acc = lin[e]*w3;
    if (tl>=1) acc += lin[e-Dm]*w2;
    if (tl>=2) acc += lin[e-2*Dm]*w1;
    if (tl>=3) acc += lin[e-3*Dm]*w0;
    float y = acc * sigm(acc);
    if (dsilu) y = y * sigm(y);
    out[e] = y;
}

__global__ void conv_mix_kernel(const float* __restrict__ cm, const float* __restrict__ mbias)
{
    int e = blockIdx.x*blockDim.x + threadIdx.x;
    if (e >= Mrows*Hh) return;
    int t = e / Hh, h = e % Hh;
    int tl = t % Lseq;
    float w0=cm[h*4+0], w1=cm[h*4+1], w2=cm[h*4+2], w3=cm[h*4+3];
    float acc = g_mixlin[e]*w3;
    if (tl>=1) acc += g_mixlin[e-Hh]*w2;
    if (tl>=2) acc += g_mixlin[e-2*Hh]*w1;
    if (tl>=3) acc += g_mixlin[e-3*Hh]*w0;
    float y = acc * sigm(acc);
    g_mix[e] = sigm(y + mbias[h]);
}

// ---------------- per-chunk precompute (register-tiled) ----------------
#define SQS 260
__global__ __launch_bounds__(256) void chunk_pre_kernel()
{
    extern __shared__ float sm4[];
    float* sq  = sm4;
    float* skk = sq  + 32*SQS;
    float* sv  = skk + 32*SQS;
    float* sT  = sv  + 32*SQS;
    float* sb  = sT  + 1024;
    int z = blockIdx.x;
    int b  = z >> 8;
    int h  = (z >> 6) & 3;
    int nc = z & 63;
    int t0 = b*Lseq + nc*CHK;
    int cb = h*DHd;
    int tid = threadIdx.x, lane = tid & 31, wid = tid >> 5;

    for (int e=tid; e<32*64; e+=256){
        int r=e>>6, c=(e&63)*4;
        *(float4*)&sq [r*SQS+c] = *(const float4*)&g_q[(size_t)(t0+r)*Dm + cb + c];
        *(float4*)&skk[r*SQS+c] = *(const float4*)&g_k[(size_t)(t0+r)*Dm + cb + c];
        *(float4*)&sv [r*SQS+c] = *(const float4*)&g_v[(size_t)(t0+r)*Dm + cb + c];
    }
    if (tid < 32) sb[tid] = g_beta[(t0+tid)*Hh + h];
    __syncthreads();

    for (int r=wid; r<32; r+=8){
        float s=0.0f;
        for (int c=lane;c<256;c+=32){ float v=sq[r*SQS+c]; s+=v*v; }
        for (int o=16;o;o>>=1) s += __shfl_xor_sync(0xffffffffu,s,o);
        float rn = rsqrtf(s + 1e-6f);
        for (int c=lane;c<256;c+=32){ sq[r*SQS+c] *= rn; }
        s=0.0f;
        for (int c=lane;c<256;c+=32){ float v=skk[r*SQS+c]; s+=v*v; }
        for (int o=16;o;o>>=1) s += __shfl_xor_sync(0xffffffffu,s,o);
        rn = rsqrtf(s + 1e-6f);
        for (int c=lane;c<256;c+=32){ skk[r*SQS+c] *= rn; }
    }
    __syncthreads();

    {
        int ti = tid >> 4, tj = tid & 15;
        int i0 = 2*ti, j0 = 2*tj;
        float a00=0,a01=0,a10=0,a11=0;
        float q00=0,q01=0,q10=0,q11=0;
#pragma unroll 8
        for (int p=0;p<256;p+=4){
            float4 ki0 = *(float4*)&skk[i0*SQS+p];
            float4 ki1 = *(float4*)&skk[(i0+1)*SQS+p];
            float4 qi0 = *(float4*)&sq [i0*SQS+p];
            float4 qi1 = *(float4*)&sq [(i0+1)*SQS+p];
            float4 kj0 = *(float4*)&skk[j0*SQS+p];
            float4 kj1 = *(float4*)&skk[(j0+1)*SQS+p];
            a00 += ki0.x*kj0.x + ki0.y*kj0.y + ki0.z*kj0.z + ki0.w*kj0.w;
            a01 += ki0.x*kj1.x + ki0.y*kj1.y + ki0.z*kj1.z + ki0.w*kj1.w;
            a10 += ki1.x*kj0.x + ki1.y*kj0.y + ki1.z*kj0.z + ki1.w*kj0.w;
            a11 += ki1.x*kj1.x + ki1.y*kj1.y + ki1.z*kj1.z + ki1.w*kj1.w;
            q00 += qi0.x*kj0.x + qi0.y*kj0.y + qi0.z*kj0.z + qi0.w*kj0.w;
            q01 += qi0.x*kj1.x + qi0.y*kj1.y + qi0.z*kj1.z + qi0.w*kj1.w;
            q10 += qi1.x*kj0.x + qi1.y*kj0.y + qi1.z*kj0.z + qi1.w*kj0.w;
            q11 += qi1.x*kj1.x + qi1.y*kj1.y + qi1.z*kj1.z + qi1.w*kj1.w;
        }
        sT[i0*32+j0]       = (j0   < i0  ) ? -sb[i0]*a00   : 0.0f;
        sT[i0*32+j0+1]     = (j0+1 < i0  ) ? -sb[i0]*a01   : 0.0f;
        sT[(i0+1)*32+j0]   = (j0   < i0+1) ? -sb[i0+1]*a10 : 0.0f;
        sT[(i0+1)*32+j0+1] = (j0+1 < i0+1) ? -sb[i0+1]*a11 : 0.0f;
        size_t abase = (size_t)z*1024;
        g_A2[abase + i0*32+j0]       = (j0   <= i0  ) ? q00 : 0.0f;
        g_A2[abase + i0*32+j0+1]     = (j0+1 <= i0  ) ? q01 : 0.0f;
        g_A2[abase + (i0+1)*32+j0]   = (j0   <= i0+1) ? q10 : 0.0f;
        g_A2[abase + (i0+1)*32+j0+1] = (j0+1 <= i0+1) ? q11 : 0.0f;
    }
    __syncthreads();

    if (wid == 0){
        for (int i=1;i<32;i++){
            float a = sT[i*32+lane];
            float acc = 0.0f;
            for (int j=1;j<32;j++){
                float aij = __shfl_sync(0xffffffffu, a, j);
                acc += aij * sT[j*32+lane];
            }
            if (lane < i) sT[i*32+lane] = a + acc;
            __syncwarp();
        }
        sT[lane*32+lane] += 1.0f;
    }
    __syncthreads();

    for (int e=tid; e<1024; e+=256) sT[e] *= sb[e&31];
    __syncthreads();

    size_t wqb = (size_t)z*16384;
    {
        int ri = tid >> 6;
        int tc = (tid & 63) * 4;
        float4 ua[8], wa[8];
#pragma unroll
        for (int r=0;r<8;r++){ ua[r]=make_float4(0,0,0,0); wa[r]=make_float4(0,0,0,0); }
        for (int j=0;j<32;j++){
            float4 v4 = *(float4*)&sv [j*SQS + tc];
            float4 k4 = *(float4*)&skk[j*SQS + tc];
#pragma unroll
            for (int r=0;r<8;r++){
                float tb = sT[(ri*8+r)*32 + j];
                ua[r].x += tb*v4.x; ua[r].y += tb*v4.y; ua[r].z += tb*v4.z; ua[r].w += tb*v4.w;
                wa[r].x += tb*k4.x; wa[r].y += tb*k4.y; wa[r].z += tb*k4.z; wa[r].w += tb*k4.w;
            }
        }
#pragma unroll
        for (int r=0;r<8;r++){
            int i = ri*8 + r;
            *(float4*)&g_u[(size_t)(t0+i)*Dm + cb + tc] = ua[r];
            *(uint2*)&g_wq16[wqb + i*256 + tc] = make_uint2(f2h2(wa[r].x, wa[r].y), f2h2(wa[r].z, wa[r].w));
            float4 q4 = *(float4*)&sq[i*SQS + tc];
            *(uint2*)&g_wq16[wqb + (32+i)*256 + tc] = make_uint2(f2h2(q4.x, q4.y), f2h2(q4.z, q4.w));
        }
    }

    size_t ktb = (size_t)z*8192;
    for (int e=tid; e<8192; e+=256){
        int r=e>>5, j=e&31;
        g_kt16[ktb + r*32 + j] = __float2half(skk[j*SQS + r]);
    }
}

// ---------------- fp16 MMA recurrence, dv-sliced ----------------
__global__ __launch_bounds__(256) void recurrence_kernel()
{
    extern __shared__ char sm5[];
    uint32_t raw = smem_u32(sm5);
    uint32_t base = (raw + 127u) & ~127u;
    char* p0 = sm5 + (base - raw);

    const uint32_t oWQ = 0, oS = 32768, oKT = 53248, oUA = 73728;
    const uint32_t oU = 76288, oA2 = 80896, oRq = 85504, oUA32 = 90112;

    uint32_t uWQ = base+oWQ, uS = base+oS, uKT = base+oKT, uUA = base+oUA;
    float* u_s  = (float*)(p0 + oU);
    float* A2_s = (float*)(p0 + oA2);
    float* Rq_s = (float*)(p0 + oRq);
    float* ua_s = (float*)(p0 + oUA32);
    char* pS = p0 + oS;
    char* pUA = p0 + oUA;

    int bx = blockIdx.x;
    int bh = bx >> 3, vb = bx & 7;
    int b = bh >> 2, h = (bx >> 3) & 3;
    int cvb = h*DHd + vb*32;
    int tid = threadIdx.x, lane = tid & 31, wid = tid >> 5;
    int rm = wid >> 1, rn = wid & 1;

    float accS[2][4][4];
#pragma unroll
    for (int tm=0;tm<2;tm++)
#pragma unroll
        for (int tn=0;tn<4;tn++)
#pragma unroll
            for (int e=0;e<4;e++) accS[tm][tn][e]=0.0f;

    for (int ci=0; ci<NCk; ci++){
        __syncthreads();
        int slot = bh*NCk + ci;
        int t0 = b*Lseq + ci*CHK;
        const __half* gwq = g_wq16 + (size_t)slot*16384;
        const __half* gkt = g_kt16 + (size_t)slot*8192;

#pragma unroll
        for (int t=0;t<8;t++){
            int c = tid + t*256;
            int row = c >> 5, col = c & 31;
            cpa16(uWQ + row*512 + ((uint32_t)(col ^ (row & 7)) << 4), gwq + c*8);
        }
#pragma unroll
        for (int t=0;t<4;t++){
            int c = tid + t*256;
            int row = c >> 2, col = c & 3;
            cpa16(uKT + row*80 + (col << 4), gkt + c*8);
        }
        {
            int row = tid >> 3, col = tid & 7;
            cpa16(base + oU + row*144 + col*16, &g_u[(size_t)(t0+row)*Dm + cvb + col*4]);
            cpa16(base + oA2 + row*144 + col*16, g_A2 + (size_t)slot*1024 + tid*4);
        }
        CP_COMMIT();

        // convert persistent S fragments -> fp16 smem [256 dk][32 n], 80B rows
#pragma unroll
        for (int tm=0;tm<2;tm++)
#pragma unroll
        for (int tn=0;tn<4;tn++){
            int r = wid*32 + tm*16 + (lane>>2);
            int c = tn*8 + (lane&3)*2;
            *(uint32_t*)(pS + r*80 + c*2)     = f2h2(accS[tm][tn][0], accS[tm][tn][1]);
            *(uint32_t*)(pS + (r+8)*80 + c*2) = f2h2(accS[tm][tn][2], accS[tm][tn][3]);
        }

        CP_WAIT(0);
        __syncthreads();

        // R = [W;Q] @ S  (m64 n32 k256)
        float accR[2][4];
#pragma unroll
        for (int j=0;j<2;j++)
#pragma unroll
            for (int e=0;e<4;e++) accR[j][e]=0.0f;

#pragma unroll 4
        for (int kk=0; kk<16; kk++){
            int arow = rm*16 + (lane & 7) + ((lane >> 3) & 1)*8;
            int achunk = kk*2 + (lane >> 4);
            uint32_t af[4];
            LDSM_X4(af[0],af[1],af[2],af[3], uWQ + arow*512 + ((uint32_t)(achunk ^ (arow & 7)) << 4));

            int krow = kk*16 + (lane & 7) + ((lane >> 3) & 1)*8;
            uint32_t boff = krow*80 + rn*32 + ((lane >> 4) << 4);
            uint32_t s0,s1,s2,s3;
            LDSM_X4T(s0,s1,s2,s3, uS + boff);
            uint32_t bh0[2] = {s0,s1}, bh1[2] = {s2,s3};

            MMAF16(accR[0], af, bh0);
            MMAF16(accR[1], af, bh1);
        }

        if (wid < 4){
#pragma unroll
            for (int j=0;j<2;j++){
                int c = rn*16 + j*8 + (lane&3)*2;
                int r1 = rm*16 + (lane>>2);
                float ua0 = u_s[r1*36+c]   - accR[j][0];
                float ua1 = u_s[r1*36+c+1] - accR[j][1];
                *(uint32_t*)(pUA + r1*80 + c*2) = f2h2(ua0, ua1);
                *(float2*)&ua_s[r1*36+c] = make_float2(ua0, ua1);
                float ua2 = u_s[(r1+8)*36+c]   - accR[j][2];
                float ua3 = u_s[(r1+8)*36+c+1] - accR[j][3];
                *(uint32_t*)(pUA + (r1+8)*80 + c*2) = f2h2(ua2, ua3);
                *(float2*)&ua_s[(r1+8)*36+c] = make_float2(ua2, ua3);
            }
        } else {
#pragma unroll
            for (int j=0;j<2;j++){
                int c = rn*16 + j*8 + (lane&3)*2;
                int r1 = (rm-2)*16 + (lane>>2);
                *(float2*)&Rq_s[r1*36+c]     = make_float2(accR[j][0], accR[j][1]);
                *(float2*)&Rq_s[(r1+8)*36+c] = make_float2(accR[j][2], accR[j][3]);
            }
        }
        __syncthreads();

        // o = Q@S + A2 @ u_adj -> global
        {
            int c = tid & 31, rb = tid >> 5;
            float o0 = Rq_s[rb*36+c], o1 = Rq_s[(rb+8)*36+c];
            float o2 = Rq_s[(rb+16)*36+c], o3 = Rq_s[(rb+24)*36+c];
#pragma unroll 8
            for (int j=0;j<32;j++){
                float uv = ua_s[j*36+c];
                o0 += A2_s[rb*36+j]*uv;
                o1 += A2_s[(rb+8)*36+j]*uv;
                o2 += A2_s[(rb+16)*36+j]*uv;
                o3 += A2_s[(rb+24)*36+j]*uv;
            }
            g_od[(size_t)(t0+rb)*Dm + cvb + c]      = o0;
            g_od[(size_t)(t0+rb+8)*Dm + cvb + c]    = o1;
            g_od[(size_t)(t0+rb+16)*Dm + cvb + c]   = o2;
            g_od[(size_t)(t0+rb+24)*Dm + cvb + c]   = o3;
        }

        // S += K^T @ u_adj
#pragma unroll
        for (int kk=0; kk<2; kk++){
            uint32_t a_f[2][4];
#pragma unroll
            for (int tm=0;tm<2;tm++){
                int mrow = wid*32 + tm*16 + (lane & 7) + ((lane >> 3) & 1)*8;
                LDSM_X4(a_f[tm][0],a_f[tm][1],a_f[tm][2],a_f[tm][3],
                        uKT + mrow*80 + kk*32 + ((lane >> 4) << 4));
            }
            uint32_t bu[4][2];
#pragma unroll
            for (int g=0; g<2; g++){
                int krow = kk*16 + (lane & 7) + ((lane >> 3) & 1)*8;
                uint32_t r0,r1,r2,r3;
                LDSM_X4T(r0,r1,r2,r3, uUA + krow*80 + g*32 + ((lane >> 4) << 4));
                bu[2*g][0]=r0; bu[2*g][1]=r1; bu[2*g+1][0]=r2; bu[2*g+1][1]=r3;
            }
#pragma unroll
            for (int tm=0;tm<2;tm++)
#pragma unroll
                for (int tn=0;tn<4;tn++)
                    MMAF16(accS[tm][tn], a_f[tm], bu[tn]);
        }
    }
}

// ---------------- EMA chunked scan ----------------
__global__ void ema_chunk_kernel()
{
    int z = blockIdx.x;
    int b = z >> 8, h = (z >> 6) & 3, nc = z & 63;
    int t0 = b*Lseq + nc*CHK;
    int cb = h*DHd;
    int c = threadIdx.x;
    float s = 0.0f, pg = 1.0f;
    for (int t=0;t<CHK;t++){
        int row = t0 + t;
        float g = g_gamma[row*Hh + h];
        float v = g_v[(size_t)row*Dm + cb + c];
        s = g*s + (1.0f-g)*v;
        pg *= g;
        g_ema[(size_t)row*Dm + cb + c] = s;
        if (c == 0) g_pg[row*Hh + h] = pg;
    }
}

__global__ void ema_seq_kernel()
{
    int bh = blockIdx.x;
    int b = bh >> 2, h = bh & 3;
    int cb = h*DHd;
    int c = threadIdx.x;
    float S = 0.0f;
    for (int j=0;j<NCk;j++){
        g_sst[(size_t)(bh*NCk + j)*DHd + c] = S;
        int rowE = b*Lseq + j*CHK + CHK-1;
        float E = g_ema[(size_t)rowE*Dm + cb + c];
        float P = g_pg[rowE*Hh + h];
        S = E + P*S;
    }
}

// ---------------- mix + rmsnorm -> fp16 output for final GEMM ----------------
__global__ __launch_bounds__(256) void combine_kernel(const float* __restrict__ rmsw)
{
    int t = blockIdx.x, c = threadIdx.x;
    int b = t / Lseq, tl = t % Lseq, chunk = tl >> 5;
    __shared__ float red[8];
    for (int h=0;h<Hh;h++){
        float mix = g_mix[t*Hh+h];
        size_t idx = (size_t)t*Dm + h*DHd + c;
        float ema = g_ema[idx] + g_pg[t*Hh+h] * g_sst[(size_t)((b*4+h)*NCk + chunk)*DHd + c];
        float o = (1.0f-mix)*g_od[idx] + mix*ema;
        float s = o*o;
        for (int off=16;off;off>>=1) s += __shfl_xor_sync(0xffffffffu,s,off);
        if ((c&31)==0) red[c>>5]=s;
        __syncthreads();
        float tot = red[0]+red[1]+red[2]+red[3]+red[4]+red[5]+red[6]+red[7];
        float scale = rsqrtf(tot*(1.0f/256.0f) + 1e-5f);
        g_oc16[idx] = __float2half(o*scale*rmsw[c]);
        __syncthreads();
    }
}

// ---------------- launcher ----------------
extern "C" void kernel_launch(void* const* d_in, const int* in_sizes, int n_in,
                              void* d_out, int out_size)
{
    const float* X    = (const float*)d_in[0];
    const float* Wq   = (const float*)d_in[1];
    const float* Wk   = (const float*)d_in[2];
    const float* Wv   = (const float*)d_in[3];
    const float* cq   = (const float*)d_in[4];
    const float* ck   = (const float*)d_in[5];
    const float* cv   = (const float*)d_in[6];
    const float* Wb   = (const float*)d_in[7];
    const float* Wdec = (const float*)d_in[8];
    const float* Wmix = (const float*)d_in[9];
    const float* cmix = (const float*)d_in[10];
    const float* mbias= (const float*)d_in[11];
    const float* rmsw = (const float*)d_in[12];
    const float* Wo   = (const float*)d_in[13];
    float* out = (float*)d_out;
    (void)in_sizes; (void)n_in; (void)out_size;

    float *p_qlin,*p_klin,*p_vlin,*p_q,*p_k,*p_v;
    __half *p_x16,*p_oc16,*p_wt16;
    cudaGetSymbolAddress((void**)&p_qlin, g_qlin);
    cudaGetSymbolAddress((void**)&p_klin, g_klin);
    cudaGetSymbolAddress((void**)&p_vlin, g_vlin);
    cudaGetSymbolAddress((void**)&p_x16,  g_x16);
    cudaGetSymbolAddress((void**)&p_oc16, g_oc16);
    cudaGetSymbolAddress((void**)&p_wt16, g_wt16);
    cudaGetSymbolAddress((void**)&p_q, g_q);
    cudaGetSymbolAddress((void**)&p_k, g_k);
    cudaGetSymbolAddress((void**)&p_v, g_v);

    const int WM = Dm*Dm;
    const int SMEMG = 2*STAGEF + 256;      // ~64.3KB

    cudaFuncSetAttribute(mma_gemm_kernel, cudaFuncAttributeMaxDynamicSharedMemorySize, SMEMG);

    tohalf_kernel<<<(MD+255)/256,256>>>(X, p_x16, MD);
    dim3 wg(32,32), wb2(32,8);
    wsplit_kernel<<<wg,wb2>>>(Wq, p_wt16 + 0*WM);
    wsplit_kernel<<<wg,wb2>>>(Wk, p_wt16 + 1*WM);
    wsplit_kernel<<<wg,wb2>>>(Wv, p_wt16 + 2*WM);
    wsplit_kernel<<<wg,wb2>>>(Wo, p_wt16 + 3*WM);

    dim3 gg3(Dm/128, Mrows/128, 3);   // fused Q,K,V
    mma_gemm_kernel<<<gg3,256,SMEMG>>>(p_x16, p_wt16, 0, p_qlin, p_klin, p_vlin);

    proj_small_kernel<<<Mrows/8,256>>>(X, Wb, Wdec, Wmix);

    dim3 cg(MD/256, 3);
    conv_silu3_kernel<<<cg,256>>>(p_qlin, p_klin, p_vlin, cq, ck, cv, p_q, p_k, p_v);
    conv_mix_kernel<<<(Mrows*Hh+255)/256,256>>>(cmix, mbias);

    const int SMEM4 = (3*32*SQS + 1024 + 32) * 4;
    cudaFuncSetAttribute(chunk_pre_kernel, cudaFuncAttributeMaxDynamicSharedMemorySize, SMEM4);
    chunk_pre_kernel<<<Bb*Hh*NCk, 256, SMEM4>>>();

    const int SMEM5 = 94720 + 256;
    cudaFuncSetAttribute(recurrence_kernel, cudaFuncAttributeMaxDynamicSharedMemorySize, SMEM5);
    recurrence_kernel<<<Bb*Hh*8, 256, SMEM5>>>();

    ema_chunk_kernel<<<Bb*Hh*NCk, 256>>>();
    ema_seq_kernel<<<Bb*Hh, 256>>>();
    combine_kernel<<<Mrows,256>>>(rmsw);

    dim3 gg1(Dm/128, Mrows/128, 1);
    mma_gemm_kernel<<<gg1,256,SMEMG>>>(p_oc16, p_wt16, 3, out, out, out);
}